// round 13
// baseline (speedup 1.0000x reference)
#include <cuda_runtime.h>
#include <cuda_bf16.h>
#include <math.h>
#include <stdint.h>

// ---------------- Problem constants ----------------
#define BB 8
#define SS 1024
#define EE 512
#define HH 8
#define PP 32
#define HID 2048
#define MM (BB*SS)          // 8192 token rows
#define E3 (3*EE)           // 1536

// ---------------- f32 scratch ----------------
__device__ float g_qkv  [MM*E3];
__device__ float g_local[MM*EE];
__device__ float g_off2 [MM*(HH*PP)];
__device__ int   g_len  [BB];
__device__ int   g_sp   [MM*PP];
__device__ float g_qd   [MM*EE];
__device__ float g_kd   [MM*EE];
__device__ float g_vd   [MM*EE];
__device__ float g_long [MM*EE];
__device__ float g_gate2[MM*EE];
__device__ float g_x1   [MM*EE];
__device__ float g_f    [MM*EE];
__device__ unsigned char g_pad[MM];
__device__ int g_mask_kind;

// ---------------- bf16 hi/lo scratch (3xBF16 GEMM operands) ----------------
__device__ __nv_bfloat16 g_xh   [MM*EE],  g_xl   [MM*EE];
__device__ __nv_bfloat16 g_loh  [MM*EE],  g_lol  [MM*EE];
__device__ __nv_bfloat16 g_off1h[MM*EE],  g_off1l[MM*EE];
__device__ __nv_bfloat16 g_latth[MM*EE],  g_lattl[MM*EE];
__device__ __nv_bfloat16 g_cath [MM*E3],  g_catl [MM*E3];
__device__ __nv_bfloat16 g_g1h  [MM*EE],  g_g1l  [MM*EE];
__device__ __nv_bfloat16 g_x1h  [MM*EE],  g_x1l  [MM*EE];
__device__ __nv_bfloat16 g_f1h  [MM*HID], g_f1l  [MM*HID];

// weight pool (hi/lo)
#define WPOOL 5636096
__device__ __nv_bfloat16 g_wh[WPOOL], g_wl[WPOOL];
// offsets into pool
#define OFF_IP 0
#define OFF_MO 786432
#define OFF_DQ 1048576
#define OFF_DK 1310720
#define OFF_DV 1572864
#define OFF_DO 1835008
#define OFF_O1 2097152
#define OFF_O2 2359296
#define OFF_G1 2490368
#define OFF_G2 3276800
#define OFF_F1 3538944
#define OFF_F2 4587520

// ---------------- helpers ----------------
__device__ __forceinline__ float warp_sum(float v) {
    #pragma unroll
    for (int o = 16; o > 0; o >>= 1) v += __shfl_xor_sync(0xffffffffu, v, o);
    return v;
}
__device__ __forceinline__ float warp_max(float v) {
    #pragma unroll
    for (int o = 16; o > 0; o >>= 1) v = fmaxf(v, __shfl_xor_sync(0xffffffffu, v, o));
    return v;
}
__device__ __forceinline__ float gelu_exact(float x) {
    return 0.5f * x * (1.0f + erff(x * 0.70710678118654752f));
}
__device__ __forceinline__ void split_bf16(float v, __nv_bfloat16& h, __nv_bfloat16& l) {
    h = __float2bfloat16(v);
    l = __float2bfloat16(v - __bfloat162float(h));
}

// ---------------- mask dtype detection + canonicalization ------------------
__global__ void detect_mask_k(const unsigned char* __restrict__ m) {
    __shared__ int s_weird, s_3f_odd, s_nz_off, s_nz;
    if (threadIdx.x == 0) { s_weird = 0; s_3f_odd = 0; s_nz_off = 0; s_nz = 0; }
    __syncthreads();
    int weird = 0, odd3f = 0, nzoff = 0, nz = 0;
    for (int i = threadIdx.x; i < MM; i += blockDim.x) {
        unsigned char v = m[i];
        if (v) {
            nz = 1;
            if (v != 1u) weird = 1;
            if (v == 0x3fu && (i & 1)) odd3f = 1;
            if ((i & 3) && v == 1u) nzoff = 1;
        }
    }
    if (weird) atomicOr(&s_weird, 1);
    if (odd3f) atomicOr(&s_3f_odd, 1);
    if (nzoff) atomicOr(&s_nz_off, 1);
    if (nz)    atomicOr(&s_nz, 1);
    __syncthreads();
    if (threadIdx.x == 0) {
        int kind;
        if (s_weird)        kind = s_3f_odd ? 3 : 2;
        else if (s_nz_off)  kind = 0;
        else if (s_nz)      kind = 1;
        else                kind = 0;
        g_mask_kind = kind;
    }
}
__global__ void convert_mask_k(const void* __restrict__ src) {
    int i = blockIdx.x * blockDim.x + threadIdx.x;
    if (i >= MM) return;
    int kind = g_mask_kind;
    unsigned char v;
    if (kind == 0)      v = (((const unsigned char*)src)[i] != 0);
    else if (kind == 1) v = (((const int*)src)[i] != 0);
    else if (kind == 2) v = (((const float*)src)[i] != 0.0f);
    else                v = (((const unsigned short*)src)[i] != 0);
    g_pad[i] = v;
}

// ---------------- fp32 -> bf16 hi/lo split ----------------
__global__ void split_k(const float* __restrict__ s, __nv_bfloat16* __restrict__ h,
                        __nv_bfloat16* __restrict__ l, int n) {
    int i = blockIdx.x * blockDim.x + threadIdx.x;
    if (i >= n) return;
    split_bf16(s[i], h[i], l[i]);
}

// ---------------- 3xBF16 GEMM ----------------
// C[M,N] = (Ah+Al)[M,K] @ (Wh+Wl)[N,K]^T + bias  (dropping Al*Wl)
// BM=128, BN=64, BK=32, 256 threads, 8 warps (4m x 2n), warp tile 32x32.
__device__ __forceinline__ void mma_bf16(float* d, const uint32_t* a, const uint32_t* b) {
    asm volatile(
        "mma.sync.aligned.m16n8k16.row.col.f32.bf16.bf16.f32 "
        "{%0,%1,%2,%3}, {%4,%5,%6,%7}, {%8,%9}, {%0,%1,%2,%3};\n"
        : "+f"(d[0]), "+f"(d[1]), "+f"(d[2]), "+f"(d[3])
        : "r"(a[0]), "r"(a[1]), "r"(a[2]), "r"(a[3]), "r"(b[0]), "r"(b[1]));
}

template<int ACT, int WF32, int WBF16>
__global__ void __launch_bounds__(256, 2)
bgemm_k(const __nv_bfloat16* __restrict__ Ah, const __nv_bfloat16* __restrict__ Al,
        const __nv_bfloat16* __restrict__ Wh, const __nv_bfloat16* __restrict__ Wl,
        const float* __restrict__ bias, float* __restrict__ C,
        __nv_bfloat16* __restrict__ Ch, __nv_bfloat16* __restrict__ Cl,
        int M, int N, int K)
{
    __shared__ __align__(16) __nv_bfloat16 sAh[128][40];
    __shared__ __align__(16) __nv_bfloat16 sAl[128][40];
    __shared__ __align__(16) __nv_bfloat16 sWh[64][40];
    __shared__ __align__(16) __nv_bfloat16 sWl[64][40];

    const int m0 = blockIdx.y * 128;
    const int n0 = blockIdx.x * 64;
    const int tid  = threadIdx.x;
    const int warp = tid >> 5, lane = tid & 31;
    const int wm = warp >> 1, wn = warp & 1;
    const int g  = lane >> 2, t4 = lane & 3;

    float acc[2][4][4];
    #pragma unroll
    for (int i = 0; i < 2; i++)
        #pragma unroll
        for (int j = 0; j < 4; j++)
            #pragma unroll
            for (int r = 0; r < 4; r++) acc[i][j][r] = 0.0f;

    const int arow0 = (tid)      >> 2, acol0 = (tid & 3) << 3;       // A part 1
    const int arow1 = (tid + 256) >> 2;                               // A part 2 (same col pattern)
    const int wrow  = tid >> 2,  wcol = (tid & 3) << 3;               // W

    for (int k0 = 0; k0 < K; k0 += 32) {
        *(uint4*)&sAh[arow0][acol0] = *(const uint4*)&Ah[(size_t)(m0 + arow0) * K + k0 + acol0];
        *(uint4*)&sAl[arow0][acol0] = *(const uint4*)&Al[(size_t)(m0 + arow0) * K + k0 + acol0];
        *(uint4*)&sAh[arow1][acol0] = *(const uint4*)&Ah[(size_t)(m0 + arow1) * K + k0 + acol0];
        *(uint4*)&sAl[arow1][acol0] = *(const uint4*)&Al[(size_t)(m0 + arow1) * K + k0 + acol0];
        *(uint4*)&sWh[wrow][wcol]   = *(const uint4*)&Wh[(size_t)(n0 + wrow) * K + k0 + wcol];
        *(uint4*)&sWl[wrow][wcol]   = *(const uint4*)&Wl[(size_t)(n0 + wrow) * K + k0 + wcol];
        __syncthreads();

        #pragma unroll
        for (int kk = 0; kk < 32; kk += 16) {
            uint32_t ah[2][4], al[2][4], bh[4][2], bl[4][2];
            const int kc = kk + 2 * t4;
            #pragma unroll
            for (int i = 0; i < 2; i++) {
                int r = wm * 32 + i * 16 + g;
                ah[i][0] = *(const uint32_t*)&sAh[r    ][kc];
                ah[i][1] = *(const uint32_t*)&sAh[r + 8][kc];
                ah[i][2] = *(const uint32_t*)&sAh[r    ][kc + 8];
                ah[i][3] = *(const uint32_t*)&sAh[r + 8][kc + 8];
                al[i][0] = *(const uint32_t*)&sAl[r    ][kc];
                al[i][1] = *(const uint32_t*)&sAl[r + 8][kc];
                al[i][2] = *(const uint32_t*)&sAl[r    ][kc + 8];
                al[i][3] = *(const uint32_t*)&sAl[r + 8][kc + 8];
            }
            #pragma unroll
            for (int j = 0; j < 4; j++) {
                int n = wn * 32 + j * 8 + g;
                bh[j][0] = *(const uint32_t*)&sWh[n][kc];
                bh[j][1] = *(const uint32_t*)&sWh[n][kc + 8];
                bl[j][0] = *(const uint32_t*)&sWl[n][kc];
                bl[j][1] = *(const uint32_t*)&sWl[n][kc + 8];
            }
            #pragma unroll
            for (int i = 0; i < 2; i++)
                #pragma unroll
                for (int j = 0; j < 4; j++) {
                    mma_bf16(acc[i][j], ah[i], bh[j]);
                    mma_bf16(acc[i][j], ah[i], bl[j]);
                    mma_bf16(acc[i][j], al[i], bh[j]);
                }
        }
        __syncthreads();
    }

    // epilogue
    #pragma unroll
    for (int i = 0; i < 2; i++) {
        int r0 = m0 + wm * 32 + i * 16 + g;
        #pragma unroll
        for (int j = 0; j < 4; j++) {
            int c = n0 + wn * 32 + j * 8 + 2 * t4;
            float b0 = bias[c], b1 = bias[c + 1];
            float v00 = acc[i][j][0] + b0, v01 = acc[i][j][1] + b1;
            float v10 = acc[i][j][2] + b0, v11 = acc[i][j][3] + b1;
            if (ACT == 1) {
                v00 = gelu_exact(v00); v01 = gelu_exact(v01);
                v10 = gelu_exact(v10); v11 = gelu_exact(v11);
            }
            if (WF32) {
                *(float2*)&C[(size_t)r0 * N + c]       = make_float2(v00, v01);
                *(float2*)&C[(size_t)(r0 + 8) * N + c] = make_float2(v10, v11);
            }
            if (WBF16) {
                __nv_bfloat16 h0, l0, h1, l1;
                split_bf16(v00, h0, l0); split_bf16(v01, h1, l1);
                *(__nv_bfloat162*)&Ch[(size_t)r0 * N + c] = __nv_bfloat162(h0, h1);
                *(__nv_bfloat162*)&Cl[(size_t)r0 * N + c] = __nv_bfloat162(l0, l1);
                split_bf16(v10, h0, l0); split_bf16(v11, h1, l1);
                *(__nv_bfloat162*)&Ch[(size_t)(r0 + 8) * N + c] = __nv_bfloat162(h0, h1);
                *(__nv_bfloat162*)&Cl[(size_t)(r0 + 8) * N + c] = __nv_bfloat162(l0, l1);
            }
        }
    }
}

// ---------------- Local windowed attention (window = 4) -> lo hi/lo --------
__global__ void local_attn_k(const float* __restrict__ qkv,
                             const unsigned char* __restrict__ pad,
                             __nv_bfloat16* __restrict__ loh,
                             __nv_bfloat16* __restrict__ lol) {
    int bq = blockIdx.x;
    int b = bq >> 10, q = bq & 1023;
    int h = threadIdx.x >> 5, lane = threadIdx.x & 31;

    const float* qr = qkv + (size_t)bq * E3 + h * 64;
    float q0 = qr[lane], q1 = qr[lane + 32];
    const float* rowbase = qkv + (size_t)(b << 10) * E3;

    float sc[4];
    #pragma unroll
    for (int w = 0; w < 4; w++) {
        int kp = q - 3 + w;
        bool valid = (kp >= 0) && (pad[(b << 10) + kp] == 0);
        float s = -INFINITY;
        if (valid) {
            const float* kr = rowbase + (size_t)kp * E3 + EE + h * 64;
            float d = q0 * kr[lane] + q1 * kr[lane + 32];
            d = warp_sum(d);
            s = d * 0.125f;
        }
        sc[w] = s;
    }
    float mx = fmaxf(fmaxf(sc[0], sc[1]), fmaxf(sc[2], sc[3]));
    float o0 = 0.0f, o1 = 0.0f;
    if (mx != -INFINITY) {
        float p[4], psum = 0.0f;
        #pragma unroll
        for (int w = 0; w < 4; w++) {
            p[w] = (sc[w] == -INFINITY) ? 0.0f : expf(sc[w] - mx);
            psum += p[w];
        }
        float inv = 1.0f / psum;
        #pragma unroll
        for (int w = 0; w < 4; w++) {
            if (p[w] != 0.0f) {
                const float* vr = rowbase + (size_t)(q - 3 + w) * E3 + 2*EE + h * 64;
                float pw = p[w] * inv;
                o0 = fmaf(pw, vr[lane], o0);
                o1 = fmaf(pw, vr[lane + 32], o1);
            }
        }
    }
    size_t i0 = (size_t)bq * EE + h * 64 + lane;
    __nv_bfloat16 hh, ll;
    split_bf16(o0, hh, ll); loh[i0] = hh;      lol[i0] = ll;
    split_bf16(o1, hh, ll); loh[i0 + 32] = hh; lol[i0 + 32] = ll;
}

// ---------------- lengths ----------------
__global__ void lengths_k(const unsigned char* __restrict__ pad, int* __restrict__ len) {
    int b = blockIdx.x, tid = threadIdx.x;
    __shared__ int red[256];
    int c = 0;
    for (int i = tid; i < SS; i += 256) c += (pad[b * SS + i] != 0);
    red[tid] = c; __syncthreads();
    for (int s = 128; s > 0; s >>= 1) { if (tid < s) red[tid] += red[tid + s]; __syncthreads(); }
    if (tid == 0) { int l = SS - red[0]; len[b] = l < 1 ? 1 : l; }
}

// ---------------- sampler ----------------
__global__ void sampler_k(const float* __restrict__ off2, const int* __restrict__ len,
                          int* __restrict__ sp) {
    int bq = blockIdx.x, b = bq >> 10, q = bq & 1023;
    int p = threadIdx.x;
    const float* r = off2 + (size_t)bq * (HH * PP);
    float o = 0.0f;
    #pragma unroll
    for (int h = 0; h < HH; h++) o += tanhf(r[h * PP + p]);
    float posf = (float)q;
    float delta = __fadd_rn(0.9f, -0.1f);
    float step  = __fdiv_rn(delta, 31.0f);
    float anchor = __fadd_rn(0.1f, __fmul_rn((float)p, step));
    float base = __fmul_rn(anchor, posf);
    float s = __fadd_rn(base, o);
    float lower = fmaxf(posf - 256.0f, 0.0f);
    s = fminf(fmaxf(s, lower), posf);
    s = fminf(s, (float)(len[b] - 1));
    sp[(size_t)bq * PP + p] = (int)rintf(s);
}

// ---------------- long deformable attention -> latt hi/lo ----------------
__global__ void long_attn_k(const float* __restrict__ qd, const float* __restrict__ kd,
                            const float* __restrict__ vd, const int* __restrict__ sp,
                            const unsigned char* __restrict__ pad,
                            __nv_bfloat16* __restrict__ outh,
                            __nv_bfloat16* __restrict__ outl) {
    int bq = blockIdx.x, b = bq >> 10, q = bq & 1023;
    __shared__ float qs[EE];
    __shared__ float pa[PP];
    __shared__ int sps[PP];
    int tid = threadIdx.x;
    const float* qr = qd + (size_t)bq * EE;
    for (int e = tid; e < EE; e += 128) qs[e] = qr[e];
    if (tid < PP) sps[tid] = sp[(size_t)bq * PP + tid];
    __syncthreads();

    int warp = tid >> 5, lane = tid & 31;
    int rb = q - 3; if (rb < 0) rb = 0;
    for (int p = warp; p < PP; p += 4) {
        int s = sps[p];
        bool inv = (pad[(b << 10) + s] != 0) || (s > q) || (s >= rb);
        float val = -INFINITY;
        if (!inv) {
            const float* kr = kd + (size_t)((b << 10) + s) * EE;
            float d = 0.0f;
            #pragma unroll 4
            for (int e = lane; e < EE; e += 32) d = fmaf(qs[e], kr[e], d);
            d = warp_sum(d);
            val = d * 0.04419417382415922f;
        }
        if (lane == 0) pa[p] = val;
    }
    __syncthreads();
    if (tid < 32) {
        float v = pa[tid];
        float mx = warp_max(v);
        float e = (mx == -INFINITY) ? 0.0f : expf(v - mx);
        float sum = warp_sum(e);
        pa[tid] = (sum > 0.0f) ? e / sum : 0.0f;
    }
    __syncthreads();
    const float* vb = vd + (size_t)(b << 10) * EE;
    for (int e = tid; e < EE; e += 128) {
        float acc = 0.0f;
        #pragma unroll
        for (int p = 0; p < PP; p++) {
            float ap = pa[p];
            if (ap != 0.0f) acc = fmaf(ap, vb[(size_t)sps[p] * EE + e], acc);
        }
        __nv_bfloat16 hh, ll;
        split_bf16(acc, hh, ll);
        outh[(size_t)bq * EE + e] = hh;
        outl[(size_t)bq * EE + e] = ll;
    }
}

// ---------------- concat [x | local | long] -> hi/lo ----------------
__global__ void concat_k(const float* __restrict__ x, const float* __restrict__ l,
                         const float* __restrict__ lg,
                         __nv_bfloat16* __restrict__ ch, __nv_bfloat16* __restrict__ cl) {
    size_t i = (size_t)blockIdx.x * blockDim.x + threadIdx.x;
    if (i >= (size_t)MM * E3) return;
    size_t row = i / E3; int c = (int)(i % E3);
    float v;
    if (c < EE)        v = x [row * EE + c];
    else if (c < 2*EE) v = l [row * EE + (c - EE)];
    else               v = lg[row * EE + (c - 2*EE)];
    __nv_bfloat16 hh, ll;
    split_bf16(v, hh, ll);
    ch[i] = hh; cl[i] = ll;
}

// ---------------- gate fuse + first residual ----------------
__global__ void fuse_k(const float* __restrict__ x, const float* __restrict__ l,
                       const float* __restrict__ lg, const float* __restrict__ gt,
                       float* __restrict__ out) {
    size_t i = (size_t)blockIdx.x * blockDim.x + threadIdx.x;
    if (i >= (size_t)MM * EE) return;
    float g = 1.0f / (1.0f + expf(-gt[i]));
    out[i] = x[i] + g * l[i] + (1.0f - g) * lg[i];
}

// ---------------- LayerNorm in-place + hi/lo emit ----------------
__global__ void ln_k(float* __restrict__ x, const float* __restrict__ g,
                     const float* __restrict__ b,
                     __nv_bfloat16* __restrict__ xh, __nv_bfloat16* __restrict__ xl) {
    int row = blockIdx.x, tid = threadIdx.x;
    float* r = x + (size_t)row * EE;
    float v0 = r[tid], v1 = r[tid + 256];
    __shared__ float red[256];
    red[tid] = v0 + v1; __syncthreads();
    for (int s = 128; s > 0; s >>= 1) { if (tid < s) red[tid] += red[tid + s]; __syncthreads(); }
    float m = red[0] * (1.0f / 512.0f);
    __syncthreads();
    float d0 = v0 - m, d1 = v1 - m;
    red[tid] = d0*d0 + d1*d1; __syncthreads();
    for (int s = 128; s > 0; s >>= 1) { if (tid < s) red[tid] += red[tid + s]; __syncthreads(); }
    float rs = rsqrtf(red[0] * (1.0f / 512.0f) + 1e-5f);
    float o0 = d0 * rs * g[tid]       + b[tid];
    float o1 = d1 * rs * g[tid + 256] + b[tid + 256];
    r[tid] = o0; r[tid + 256] = o1;
    __nv_bfloat16 hh, ll;
    size_t base = (size_t)row * EE;
    split_bf16(o0, hh, ll); xh[base + tid] = hh;       xl[base + tid] = ll;
    split_bf16(o1, hh, ll); xh[base + tid + 256] = hh; xl[base + tid + 256] = ll;
}

// ---------------- residual + LayerNorm -> dst ----------------
__global__ void resln_k(const float* __restrict__ a, const float* __restrict__ c,
                        const float* __restrict__ g, const float* __restrict__ b,
                        float* __restrict__ dst) {
    int row = blockIdx.x, tid = threadIdx.x;
    size_t off = (size_t)row * EE;
    float v0 = a[off + tid] + c[off + tid];
    float v1 = a[off + tid + 256] + c[off + tid + 256];
    __shared__ float red[256];
    red[tid] = v0 + v1; __syncthreads();
    for (int s = 128; s > 0; s >>= 1) { if (tid < s) red[tid] += red[tid + s]; __syncthreads(); }
    float m = red[0] * (1.0f / 512.0f);
    __syncthreads();
    float d0 = v0 - m, d1 = v1 - m;
    red[tid] = d0*d0 + d1*d1; __syncthreads();
    for (int s = 128; s > 0; s >>= 1) { if (tid < s) red[tid] += red[tid + s]; __syncthreads(); }
    float rs = rsqrtf(red[0] * (1.0f / 512.0f) + 1e-5f);
    dst[off + tid]       = d0 * rs * g[tid]       + b[tid];
    dst[off + tid + 256] = d1 * rs * g[tid + 256] + b[tid + 256];
}

// ---------------- launch ----------------
static inline void* sym(const void* s) {
    void* p = nullptr;
    cudaGetSymbolAddress(&p, s);
    return p;
}

extern "C" void kernel_launch(void* const* d_in, const int* in_sizes, int n_in,
                              void* d_out, int out_size) {
    const float* x   = (const float*)d_in[0];
    const void*  padsrc = d_in[1];
    const float* ipw = (const float*)d_in[2];  const float* ipb = (const float*)d_in[3];
    const float* mow = (const float*)d_in[4];  const float* mob = (const float*)d_in[5];
    const float* dqw = (const float*)d_in[6];  const float* dqb = (const float*)d_in[7];
    const float* dkw = (const float*)d_in[8];  const float* dkb = (const float*)d_in[9];
    const float* dvw = (const float*)d_in[10]; const float* dvb = (const float*)d_in[11];
    const float* dow = (const float*)d_in[12]; const float* dob = (const float*)d_in[13];
    const float* o1w = (const float*)d_in[14]; const float* o1b = (const float*)d_in[15];
    const float* o2w = (const float*)d_in[16]; const float* o2b = (const float*)d_in[17];
    const float* g1w = (const float*)d_in[18]; const float* g1b = (const float*)d_in[19];
    const float* g2w = (const float*)d_in[20]; const float* g2b = (const float*)d_in[21];
    const float* n1g = (const float*)d_in[22]; const float* n1b = (const float*)d_in[23];
    const float* n2g = (const float*)d_in[24]; const float* n2b = (const float*)d_in[25];
    const float* f1w = (const float*)d_in[26]; const float* f1b = (const float*)d_in[27];
    const float* f2w = (const float*)d_in[28]; const float* f2b = (const float*)d_in[29];
    float* out = (float*)d_out;

    float* qkv   = (float*)sym(g_qkv);
    float* loc   = (float*)sym(g_local);
    float* off2  = (float*)sym(g_off2);
    int*   len   = (int*)  sym(g_len);
    int*   sp    = (int*)  sym(g_sp);
    float* qd    = (float*)sym(g_qd);
    float* kd    = (float*)sym(g_kd);
    float* vd    = (float*)sym(g_vd);
    float* lng   = (float*)sym(g_long);
    float* gate2 = (float*)sym(g_gate2);
    float* x1    = (float*)sym(g_x1);
    float* f     = (float*)sym(g_f);
    unsigned char* pad = (unsigned char*)sym(g_pad);

    __nv_bfloat16* xh    = (__nv_bfloat16*)sym(g_xh);    __nv_bfloat16* xl    = (__nv_bfloat16*)sym(g_xl);
    __nv_bfloat16* loh   = (__nv_bfloat16*)sym(g_loh);   __nv_bfloat16* lol   = (__nv_bfloat16*)sym(g_lol);
    __nv_bfloat16* off1h = (__nv_bfloat16*)sym(g_off1h); __nv_bfloat16* off1l = (__nv_bfloat16*)sym(g_off1l);
    __nv_bfloat16* latth = (__nv_bfloat16*)sym(g_latth); __nv_bfloat16* lattl = (__nv_bfloat16*)sym(g_lattl);
    __nv_bfloat16* cath  = (__nv_bfloat16*)sym(g_cath);  __nv_bfloat16* catl  = (__nv_bfloat16*)sym(g_catl);
    __nv_bfloat16* g1h   = (__nv_bfloat16*)sym(g_g1h);   __nv_bfloat16* g1l   = (__nv_bfloat16*)sym(g_g1l);
    __nv_bfloat16* x1h   = (__nv_bfloat16*)sym(g_x1h);   __nv_bfloat16* x1l   = (__nv_bfloat16*)sym(g_x1l);
    __nv_bfloat16* f1h   = (__nv_bfloat16*)sym(g_f1h);   __nv_bfloat16* f1l   = (__nv_bfloat16*)sym(g_f1l);
    __nv_bfloat16* wh    = (__nv_bfloat16*)sym(g_wh);    __nv_bfloat16* wl    = (__nv_bfloat16*)sym(g_wl);

    const int M = MM;
    dim3 thr(256);

    // 0. canonicalize padding mask
    detect_mask_k<<<1, 256>>>((const unsigned char*)padsrc);
    convert_mask_k<<<(MM + 255)/256, thr>>>(padsrc);

    // 1. splits: x + all weights
    auto SPLIT = [&](const float* s, __nv_bfloat16* h, __nv_bfloat16* l, int n) {
        split_k<<<(n + 255)/256, thr>>>(s, h, l, n);
    };
    SPLIT(x,   xh,           xl,           MM*EE);
    SPLIT(ipw, wh + OFF_IP,  wl + OFF_IP,  E3*EE);
    SPLIT(mow, wh + OFF_MO,  wl + OFF_MO,  EE*EE);
    SPLIT(dqw, wh + OFF_DQ,  wl + OFF_DQ,  EE*EE);
    SPLIT(dkw, wh + OFF_DK,  wl + OFF_DK,  EE*EE);
    SPLIT(dvw, wh + OFF_DV,  wl + OFF_DV,  EE*EE);
    SPLIT(dow, wh + OFF_DO,  wl + OFF_DO,  EE*EE);
    SPLIT(o1w, wh + OFF_O1,  wl + OFF_O1,  EE*EE);
    SPLIT(o2w, wh + OFF_O2,  wl + OFF_O2,  (HH*PP)*EE);
    SPLIT(g1w, wh + OFF_G1,  wl + OFF_G1,  EE*E3);
    SPLIT(g2w, wh + OFF_G2,  wl + OFF_G2,  EE*EE);
    SPLIT(f1w, wh + OFF_F1,  wl + OFF_F1,  HID*EE);
    SPLIT(f2w, wh + OFF_F2,  wl + OFF_F2,  EE*HID);

    // 2. qkv projection (f32 out)
    bgemm_k<0,1,0><<<dim3(E3/64, M/128), thr>>>(xh, xl, wh+OFF_IP, wl+OFF_IP, ipb,
                                                qkv, nullptr, nullptr, M, E3, EE);
    // 3. local attention -> lo hi/lo
    local_attn_k<<<M, 256>>>(qkv, pad, loh, lol);
    // 4. mha out proj (f32)
    bgemm_k<0,1,0><<<dim3(EE/64, M/128), thr>>>(loh, lol, wh+OFF_MO, wl+OFF_MO, mob,
                                                loc, nullptr, nullptr, M, EE, EE);
    // 5. offset mlp: off1 = GELU(x@o1) -> bf16 only; off2 (f32)
    bgemm_k<1,0,1><<<dim3(EE/64, M/128), thr>>>(xh, xl, wh+OFF_O1, wl+OFF_O1, o1b,
                                                nullptr, off1h, off1l, M, EE, EE);
    bgemm_k<0,1,0><<<dim3((HH*PP)/64, M/128), thr>>>(off1h, off1l, wh+OFF_O2, wl+OFF_O2, o2b,
                                                off2, nullptr, nullptr, M, HH*PP, EE);
    // 6. lengths + sampled positions
    lengths_k<<<BB, 256>>>(pad, len);
    sampler_k<<<M, PP>>>(off2, len, sp);
    // 7. deformable q/k/v projections (f32)
    bgemm_k<0,1,0><<<dim3(EE/64, M/128), thr>>>(xh, xl, wh+OFF_DQ, wl+OFF_DQ, dqb,
                                                qd, nullptr, nullptr, M, EE, EE);
    bgemm_k<0,1,0><<<dim3(EE/64, M/128), thr>>>(xh, xl, wh+OFF_DK, wl+OFF_DK, dkb,
                                                kd, nullptr, nullptr, M, EE, EE);
    bgemm_k<0,1,0><<<dim3(EE/64, M/128), thr>>>(xh, xl, wh+OFF_DV, wl+OFF_DV, dvb,
                                                vd, nullptr, nullptr, M, EE, EE);
    // 8. long attention -> latt hi/lo; out proj (f32)
    long_attn_k<<<M, 128>>>(qd, kd, vd, sp, pad, latth, lattl);
    bgemm_k<0,1,0><<<dim3(EE/64, M/128), thr>>>(latth, lattl, wh+OFF_DO, wl+OFF_DO, dob,
                                                lng, nullptr, nullptr, M, EE, EE);
    // 9. gating
    concat_k<<<(MM*E3 + 255)/256, thr>>>(x, loc, lng, cath, catl);
    bgemm_k<1,0,1><<<dim3(EE/64, M/128), thr>>>(cath, catl, wh+OFF_G1, wl+OFF_G1, g1b,
                                                nullptr, g1h, g1l, M, EE, E3);
    bgemm_k<0,1,0><<<dim3(EE/64, M/128), thr>>>(g1h, g1l, wh+OFF_G2, wl+OFF_G2, g2b,
                                                gate2, nullptr, nullptr, M, EE, EE);
    fuse_k<<<(MM*EE + 255)/256, thr>>>(x, loc, lng, gate2, x1);
    ln_k<<<M, 256>>>(x1, n1g, n1b, x1h, x1l);
    // 10. FFN
    bgemm_k<1,0,1><<<dim3(HID/64, M/128), thr>>>(x1h, x1l, wh+OFF_F1, wl+OFF_F1, f1b,
                                                nullptr, f1h, f1l, M, HID, EE);
    bgemm_k<0,1,0><<<dim3(EE/64, M/128), thr>>>(f1h, f1l, wh+OFF_F2, wl+OFF_F2, f2b,
                                                f, nullptr, nullptr, M, EE, HID);
    // 11. final residual + LN -> output
    resln_k<<<M, 256>>>(x1, f, n2g, n2b, out);

    (void)in_sizes; (void)n_in; (void)out_size;
}

// round 14
// speedup vs baseline: 1.2859x; 1.2859x over previous
#include <cuda_runtime.h>
#include <cuda_bf16.h>
#include <math.h>
#include <stdint.h>

// ---------------- Problem constants ----------------
#define BB 8
#define SS 1024
#define EE 512
#define HH 8
#define PP 32
#define HID 2048
#define MM (BB*SS)          // 8192 token rows
#define E3 (3*EE)           // 1536

// ---------------- f32 scratch ----------------
__device__ float g_qkv  [MM*E3];
__device__ float g_qkvd [MM*E3];
__device__ float g_local[MM*EE];
__device__ float g_off2 [MM*(HH*PP)];
__device__ int   g_len  [BB];
__device__ int   g_sp   [MM*PP];
__device__ float g_long [MM*EE];
__device__ float g_x1   [MM*EE];
__device__ float g_f    [MM*EE];
__device__ float g_b3   [E3];
__device__ unsigned char g_pad[MM];
__device__ int g_mask_kind;

// ---------------- bf16 hi/lo scratch ----------------
__device__ __align__(16) __nv_bfloat16 g_xh   [MM*EE],  g_xl   [MM*EE];
__device__ __align__(16) __nv_bfloat16 g_loh  [MM*EE],  g_lol  [MM*EE];
__device__ __align__(16) __nv_bfloat16 g_loch [MM*EE],  g_locl [MM*EE];
__device__ __align__(16) __nv_bfloat16 g_lngh [MM*EE],  g_lngl [MM*EE];
__device__ __align__(16) __nv_bfloat16 g_off1h[MM*EE],  g_off1l[MM*EE];
__device__ __align__(16) __nv_bfloat16 g_latth[MM*EE],  g_lattl[MM*EE];
__device__ __align__(16) __nv_bfloat16 g_g1h  [MM*EE],  g_g1l  [MM*EE];
__device__ __align__(16) __nv_bfloat16 g_x1h  [MM*EE],  g_x1l  [MM*EE];
__device__ __align__(16) __nv_bfloat16 g_f1h  [MM*HID], g_f1l  [MM*HID];

// weight pool (hi/lo)
#define WPOOL 5636096
__device__ __align__(16) __nv_bfloat16 g_wh[WPOOL], g_wl[WPOOL];
#define OFF_IP 0
#define OFF_MO 786432
#define OFF_DQ 1048576
#define OFF_DK 1310720
#define OFF_DV 1572864
#define OFF_DO 1835008
#define OFF_O1 2097152
#define OFF_O2 2359296
#define OFF_G1 2490368
#define OFF_G2 3276800
#define OFF_F1 3538944
#define OFF_F2 4587520

// ---------------- helpers ----------------
__device__ __forceinline__ float warp_sum(float v) {
    #pragma unroll
    for (int o = 16; o > 0; o >>= 1) v += __shfl_xor_sync(0xffffffffu, v, o);
    return v;
}
__device__ __forceinline__ float warp_max(float v) {
    #pragma unroll
    for (int o = 16; o > 0; o >>= 1) v = fmaxf(v, __shfl_xor_sync(0xffffffffu, v, o));
    return v;
}
__device__ __forceinline__ float gelu_exact(float x) {
    return 0.5f * x * (1.0f + erff(x * 0.70710678118654752f));
}
__device__ __forceinline__ void split_bf16(float v, __nv_bfloat16& h, __nv_bfloat16& l) {
    h = __float2bfloat16(v);
    l = __float2bfloat16(v - __bfloat162float(h));
}

// ---------------- mask dtype detection + canonicalization ------------------
__global__ void detect_mask_k(const unsigned char* __restrict__ m) {
    __shared__ int s_weird, s_3f_odd, s_nz_off, s_nz;
    if (threadIdx.x == 0) { s_weird = 0; s_3f_odd = 0; s_nz_off = 0; s_nz = 0; }
    __syncthreads();
    int weird = 0, odd3f = 0, nzoff = 0, nz = 0;
    for (int i = threadIdx.x; i < MM; i += blockDim.x) {
        unsigned char v = m[i];
        if (v) {
            nz = 1;
            if (v != 1u) weird = 1;
            if (v == 0x3fu && (i & 1)) odd3f = 1;
            if ((i & 3) && v == 1u) nzoff = 1;
        }
    }
    if (weird) atomicOr(&s_weird, 1);
    if (odd3f) atomicOr(&s_3f_odd, 1);
    if (nzoff) atomicOr(&s_nz_off, 1);
    if (nz)    atomicOr(&s_nz, 1);
    __syncthreads();
    if (threadIdx.x == 0) {
        int kind;
        if (s_weird)        kind = s_3f_odd ? 3 : 2;
        else if (s_nz_off)  kind = 0;
        else if (s_nz)      kind = 1;
        else                kind = 0;
        g_mask_kind = kind;
    }
}
__global__ void convert_mask_k(const void* __restrict__ src) {
    int i = blockIdx.x * blockDim.x + threadIdx.x;
    if (i >= MM) return;
    int kind = g_mask_kind;
    unsigned char v;
    if (kind == 0)      v = (((const unsigned char*)src)[i] != 0);
    else if (kind == 1) v = (((const int*)src)[i] != 0);
    else if (kind == 2) v = (((const float*)src)[i] != 0.0f);
    else                v = (((const unsigned short*)src)[i] != 0);
    g_pad[i] = v;
}

// ---------------- merged hi/lo split: 13 segments, one launch ---------------
#define NSEG 13
struct SplitArgs {
    const float* src[NSEG];
    __nv_bfloat16* dh[NSEG];
    __nv_bfloat16* dl[NSEG];
};
__constant__ int c_cum[NSEG + 1] = {
    0, 16384, 19456, 20480, 21504, 22528, 23552, 24576,
    25600, 26112, 29184, 30208, 34304, 38400 };
#define SPLIT_BLOCKS 38400

__global__ void megasplit_k(SplitArgs args) {
    int blk = blockIdx.x;
    int seg = 0;
    #pragma unroll
    for (int s = 1; s < NSEG; s++) if (blk >= c_cum[s]) seg = s;
    int idx = (blk - c_cum[seg]) * 256 + threadIdx.x;
    float v = args.src[seg][idx];
    __nv_bfloat16 h, l;
    split_bf16(v, h, l);
    args.dh[seg][idx] = h;
    args.dl[seg][idx] = l;
}

// ---------------- bias concat for merged dq/dk/dv GEMM ----------------
__global__ void bias3_k(const float* __restrict__ a, const float* __restrict__ b,
                        const float* __restrict__ c, float* __restrict__ o) {
    int i = blockIdx.x * 256 + threadIdx.x;
    if (i >= E3) return;
    o[i] = (i < 512) ? a[i] : (i < 1024 ? b[i - 512] : c[i - 1024]);
}

// ---------------- 3xBF16 pipelined GEMM ----------------
// C[M,N] = (Ah+Al)[M,K] @ (Wh+Wl)[N,K]^T + bias  (dropping Al*Wl)
// BM=128 BN=64 BK=32, 256 thr, 8 warps (4m x 2n), warp tile 32x32.
// 2-stage cp.async pipeline, ldmatrix fragment loads.
// ACT: 0 none, 1 GELU, 2 gate-fuse (out = P0 + sig(v)*P1 + (1-sig)*P2), 3 v += P0.
// SEG: A operand read segment-wise from (Ah,Al | AhB,AlB | AhC,AlC), each [M,512].
__device__ __forceinline__ void mma_bf16(float* d, const uint32_t* a, const uint32_t* b) {
    asm volatile(
        "mma.sync.aligned.m16n8k16.row.col.f32.bf16.bf16.f32 "
        "{%0,%1,%2,%3}, {%4,%5,%6,%7}, {%8,%9}, {%0,%1,%2,%3};\n"
        : "+f"(d[0]), "+f"(d[1]), "+f"(d[2]), "+f"(d[3])
        : "r"(a[0]), "r"(a[1]), "r"(a[2]), "r"(a[3]), "r"(b[0]), "r"(b[1]));
}
__device__ __forceinline__ void ldsm4(uint32_t* r, uint32_t addr) {
    asm volatile("ldmatrix.sync.aligned.m8n8.x4.shared.b16 {%0,%1,%2,%3}, [%4];\n"
        : "=r"(r[0]), "=r"(r[1]), "=r"(r[2]), "=r"(r[3]) : "r"(addr));
}
__device__ __forceinline__ void cp16(uint32_t dst, const void* src) {
    asm volatile("cp.async.cg.shared.global [%0], [%1], 16;\n" :: "r"(dst), "l"(src));
}
template<int N> __device__ __forceinline__ void cp_wait() {
    asm volatile("cp.async.wait_group %0;\n" :: "n"(N));
}

#define STG_BYTES 30720u   // per stage: Ah 10240 | Al 10240 | Wh 5120 | Wl 5120
#define SMEM_BYTES (2*STG_BYTES)

template<int ACT, int WF32, int WBF16, int SEG>
__global__ void __launch_bounds__(256, 2)
bgemm_k(const __nv_bfloat16* __restrict__ Ah, const __nv_bfloat16* __restrict__ Al,
        const __nv_bfloat16* __restrict__ AhB, const __nv_bfloat16* __restrict__ AlB,
        const __nv_bfloat16* __restrict__ AhC, const __nv_bfloat16* __restrict__ AlC,
        const __nv_bfloat16* __restrict__ Wh, const __nv_bfloat16* __restrict__ Wl,
        const float* __restrict__ bias, float* __restrict__ C,
        __nv_bfloat16* __restrict__ Ch, __nv_bfloat16* __restrict__ Cl,
        const float* __restrict__ P0, const float* __restrict__ P1,
        const float* __restrict__ P2,
        int M, int N, int K)
{
    extern __shared__ __align__(16) char dynsm[];
    const uint32_t smem_u32 = (uint32_t)__cvta_generic_to_shared(dynsm);

    const int m0 = blockIdx.y * 128;
    const int n0 = blockIdx.x * 64;
    const int tid  = threadIdx.x;
    const int warp = tid >> 5, lane = tid & 31;
    const int wm = warp >> 1, wn = warp & 1;
    const int g  = lane >> 2, t4 = lane & 3;

    float acc[2][4][4];
    #pragma unroll
    for (int i = 0; i < 2; i++)
        #pragma unroll
        for (int j = 0; j < 4; j++)
            #pragma unroll
            for (int r = 0; r < 4; r++) acc[i][j][r] = 0.0f;

    const int lr = tid >> 2;           // 0..63
    const int c8 = (tid & 3) << 3;     // 0,8,16,24

    auto load_stage = [&](int stage, int k0) {
        uint32_t sb = smem_u32 + (uint32_t)stage * STG_BYTES;
        const __nv_bfloat16* pAh = Ah;
        const __nv_bfloat16* pAl = Al;
        int kl = k0;
        size_t as = (size_t)K;
        if (SEG) {
            as = 512;
            if (k0 >= 1024)     { pAh = AhC; pAl = AlC; kl = k0 - 1024; }
            else if (k0 >= 512) { pAh = AhB; pAl = AlB; kl = k0 - 512; }
        }
        uint32_t dA = sb + (uint32_t)(lr * 80 + c8 * 2);
        cp16(dA,                pAh + (size_t)(m0 + lr) * as + kl + c8);
        cp16(dA + 64u*80u,      pAh + (size_t)(m0 + lr + 64) * as + kl + c8);
        cp16(dA + 10240u,       pAl + (size_t)(m0 + lr) * as + kl + c8);
        cp16(dA + 10240u + 64u*80u, pAl + (size_t)(m0 + lr + 64) * as + kl + c8);
        uint32_t dW = sb + 20480u + (uint32_t)(lr * 80 + c8 * 2);
        cp16(dW,           Wh + (size_t)(n0 + lr) * K + k0 + c8);
        cp16(dW + 5120u,   Wl + (size_t)(n0 + lr) * K + k0 + c8);
    };

    // lane-invariant fragment base offsets (within a stage)
    const uint32_t aOff = (uint32_t)((wm*32 + (lane & 15)) * 80 + ((lane >> 4) << 3) * 2);
    const uint32_t bOff = 20480u + (uint32_t)(
        ((wn*32) + (lane & 7) + (((lane >> 4) & 1) << 3)) * 80 + (((lane >> 3) & 1) << 3) * 2);

    load_stage(0, 0);
    asm volatile("cp.async.commit_group;\n");
    const int niter = K >> 5;

    for (int it = 0; it < niter; ++it) {
        if (it + 1 < niter) {
            load_stage((it + 1) & 1, (it + 1) << 5);
            asm volatile("cp.async.commit_group;\n");
            cp_wait<1>();
        } else {
            cp_wait<0>();
        }
        __syncthreads();

        uint32_t sb = smem_u32 + (uint32_t)(it & 1) * STG_BYTES;
        uint32_t aB = sb + aOff;
        uint32_t bB = sb + bOff;
        #pragma unroll
        for (int kk = 0; kk < 32; kk += 16) {
            uint32_t ah[2][4], alr[2][4], bh[2][4], blr[2][4];
            ldsm4(ah[0],  aB + kk*2);
            ldsm4(ah[1],  aB + 1280u + kk*2);
            ldsm4(alr[0], aB + 10240u + kk*2);
            ldsm4(alr[1], aB + 10240u + 1280u + kk*2);
            ldsm4(bh[0],  bB + kk*2);
            ldsm4(bh[1],  bB + 1280u + kk*2);
            ldsm4(blr[0], bB + 5120u + kk*2);
            ldsm4(blr[1], bB + 5120u + 1280u + kk*2);
            #pragma unroll
            for (int i = 0; i < 2; i++)
                #pragma unroll
                for (int jp = 0; jp < 2; jp++) {
                    mma_bf16(acc[i][jp*2],   ah[i],  &bh[jp][0]);
                    mma_bf16(acc[i][jp*2+1], ah[i],  &bh[jp][2]);
                    mma_bf16(acc[i][jp*2],   ah[i],  &blr[jp][0]);
                    mma_bf16(acc[i][jp*2+1], ah[i],  &blr[jp][2]);
                    mma_bf16(acc[i][jp*2],   alr[i], &bh[jp][0]);
                    mma_bf16(acc[i][jp*2+1], alr[i], &bh[jp][2]);
                }
        }
        __syncthreads();
    }

    // epilogue
    #pragma unroll
    for (int i = 0; i < 2; i++) {
        int r0 = m0 + wm * 32 + i * 16 + g;
        #pragma unroll
        for (int j = 0; j < 4; j++) {
            int c = n0 + wn * 32 + j * 8 + 2 * t4;
            float b0 = bias[c], b1 = bias[c + 1];
            float v00 = acc[i][j][0] + b0, v01 = acc[i][j][1] + b1;
            float v10 = acc[i][j][2] + b0, v11 = acc[i][j][3] + b1;
            size_t i0 = (size_t)r0 * N + c, i1 = (size_t)(r0 + 8) * N + c;
            if (ACT == 1) {
                v00 = gelu_exact(v00); v01 = gelu_exact(v01);
                v10 = gelu_exact(v10); v11 = gelu_exact(v11);
            }
            if (ACT == 2) {
                float s00 = 1.0f/(1.0f + expf(-v00)), s01 = 1.0f/(1.0f + expf(-v01));
                float s10 = 1.0f/(1.0f + expf(-v10)), s11 = 1.0f/(1.0f + expf(-v11));
                v00 = P0[i0]   + s00 * P1[i0]   + (1.0f - s00) * P2[i0];
                v01 = P0[i0+1] + s01 * P1[i0+1] + (1.0f - s01) * P2[i0+1];
                v10 = P0[i1]   + s10 * P1[i1]   + (1.0f - s10) * P2[i1];
                v11 = P0[i1+1] + s11 * P1[i1+1] + (1.0f - s11) * P2[i1+1];
            }
            if (ACT == 3) {
                v00 += P0[i0]; v01 += P0[i0+1]; v10 += P0[i1]; v11 += P0[i1+1];
            }
            if (WF32) {
                *(float2*)&C[i0] = make_float2(v00, v01);
                *(float2*)&C[i1] = make_float2(v10, v11);
            }
            if (WBF16) {
                __nv_bfloat16 h0, l0, h1, l1;
                split_bf16(v00, h0, l0); split_bf16(v01, h1, l1);
                *(__nv_bfloat162*)&Ch[i0] = __nv_bfloat162(h0, h1);
                *(__nv_bfloat162*)&Cl[i0] = __nv_bfloat162(l0, l1);
                split_bf16(v10, h0, l0); split_bf16(v11, h1, l1);
                *(__nv_bfloat162*)&Ch[i1] = __nv_bfloat162(h0, h1);
                *(__nv_bfloat162*)&Cl[i1] = __nv_bfloat162(l0, l1);
            }
        }
    }
}

// ---------------- Local windowed attention (window = 4) -> lo hi/lo --------
__global__ void local_attn_k(const float* __restrict__ qkv,
                             const unsigned char* __restrict__ pad,
                             __nv_bfloat16* __restrict__ loh,
                             __nv_bfloat16* __restrict__ lol) {
    int bq = blockIdx.x;
    int b = bq >> 10, q = bq & 1023;
    int h = threadIdx.x >> 5, lane = threadIdx.x & 31;

    const float* qr = qkv + (size_t)bq * E3 + h * 64;
    float q0 = qr[lane], q1 = qr[lane + 32];
    const float* rowbase = qkv + (size_t)(b << 10) * E3;

    float sc[4];
    #pragma unroll
    for (int w = 0; w < 4; w++) {
        int kp = q - 3 + w;
        bool valid = (kp >= 0) && (pad[(b << 10) + kp] == 0);
        float s = -INFINITY;
        if (valid) {
            const float* kr = rowbase + (size_t)kp * E3 + EE + h * 64;
            float d = q0 * kr[lane] + q1 * kr[lane + 32];
            d = warp_sum(d);
            s = d * 0.125f;
        }
        sc[w] = s;
    }
    float mx = fmaxf(fmaxf(sc[0], sc[1]), fmaxf(sc[2], sc[3]));
    float o0 = 0.0f, o1 = 0.0f;
    if (mx != -INFINITY) {
        float p[4], psum = 0.0f;
        #pragma unroll
        for (int w = 0; w < 4; w++) {
            p[w] = (sc[w] == -INFINITY) ? 0.0f : expf(sc[w] - mx);
            psum += p[w];
        }
        float inv = 1.0f / psum;
        #pragma unroll
        for (int w = 0; w < 4; w++) {
            if (p[w] != 0.0f) {
                const float* vr = rowbase + (size_t)(q - 3 + w) * E3 + 2*EE + h * 64;
                float pw = p[w] * inv;
                o0 = fmaf(pw, vr[lane], o0);
                o1 = fmaf(pw, vr[lane + 32], o1);
            }
        }
    }
    size_t i0 = (size_t)bq * EE + h * 64 + lane;
    __nv_bfloat16 hh, ll;
    split_bf16(o0, hh, ll); loh[i0] = hh;      lol[i0] = ll;
    split_bf16(o1, hh, ll); loh[i0 + 32] = hh; lol[i0 + 32] = ll;
}

// ---------------- lengths ----------------
__global__ void lengths_k(const unsigned char* __restrict__ pad, int* __restrict__ len) {
    int b = blockIdx.x, tid = threadIdx.x;
    __shared__ int red[256];
    int c = 0;
    for (int i = tid; i < SS; i += 256) c += (pad[b * SS + i] != 0);
    red[tid] = c; __syncthreads();
    for (int s = 128; s > 0; s >>= 1) { if (tid < s) red[tid] += red[tid + s]; __syncthreads(); }
    if (tid == 0) { int l = SS - red[0]; len[b] = l < 1 ? 1 : l; }
}

// ---------------- sampler ----------------
__global__ void sampler_k(const float* __restrict__ off2, const int* __restrict__ len,
                          int* __restrict__ sp) {
    int bq = blockIdx.x, b = bq >> 10, q = bq & 1023;
    int p = threadIdx.x;
    const float* r = off2 + (size_t)bq * (HH * PP);
    float o = 0.0f;
    #pragma unroll
    for (int h = 0; h < HH; h++) o += tanhf(r[h * PP + p]);
    float posf = (float)q;
    float delta = __fadd_rn(0.9f, -0.1f);
    float step  = __fdiv_rn(delta, 31.0f);
    float anchor = __fadd_rn(0.1f, __fmul_rn((float)p, step));
    float base = __fmul_rn(anchor, posf);
    float s = __fadd_rn(base, o);
    float lower = fmaxf(posf - 256.0f, 0.0f);
    s = fminf(fmaxf(s, lower), posf);
    s = fminf(s, (float)(len[b] - 1));
    sp[(size_t)bq * PP + p] = (int)rintf(s);
}

// ---------------- long deformable attention (qkvd stride E3) ---------------
__global__ void long_attn_k(const float* __restrict__ qkvd, const int* __restrict__ sp,
                            const unsigned char* __restrict__ pad,
                            __nv_bfloat16* __restrict__ outh,
                            __nv_bfloat16* __restrict__ outl) {
    int bq = blockIdx.x, b = bq >> 10, q = bq & 1023;
    __shared__ float qs[EE];
    __shared__ float pa[PP];
    __shared__ int sps[PP];
    int tid = threadIdx.x;
    const float* qr = qkvd + (size_t)bq * E3;                // qd at offset 0
    for (int e = tid; e < EE; e += 128) qs[e] = qr[e];
    if (tid < PP) sps[tid] = sp[(size_t)bq * PP + tid];
    __syncthreads();

    int warp = tid >> 5, lane = tid & 31;
    int rb = q - 3; if (rb < 0) rb = 0;
    for (int p = warp; p < PP; p += 4) {
        int s = sps[p];
        bool inv = (pad[(b << 10) + s] != 0) || (s > q) || (s >= rb);
        float val = -INFINITY;
        if (!inv) {
            const float* kr = qkvd + (size_t)((b << 10) + s) * E3 + EE;   // kd
            float d = 0.0f;
            #pragma unroll 4
            for (int e = lane; e < EE; e += 32) d = fmaf(qs[e], kr[e], d);
            d = warp_sum(d);
            val = d * 0.04419417382415922f;
        }
        if (lane == 0) pa[p] = val;
    }
    __syncthreads();
    if (tid < 32) {
        float v = pa[tid];
        float mx = warp_max(v);
        float e = (mx == -INFINITY) ? 0.0f : expf(v - mx);
        float sum = warp_sum(e);
        pa[tid] = (sum > 0.0f) ? e / sum : 0.0f;
    }
    __syncthreads();
    const float* vb = qkvd + (size_t)(b << 10) * E3 + 2*EE;   // vd
    for (int e = tid; e < EE; e += 128) {
        float acc = 0.0f;
        #pragma unroll
        for (int p = 0; p < PP; p++) {
            float ap = pa[p];
            if (ap != 0.0f) acc = fmaf(ap, vb[(size_t)sps[p] * E3 + e], acc);
        }
        __nv_bfloat16 hh, ll;
        split_bf16(acc, hh, ll);
        outh[(size_t)bq * EE + e] = hh;
        outl[(size_t)bq * EE + e] = ll;
    }
}

// ---------------- LayerNorm in-place + hi/lo emit ----------------
__global__ void ln_k(float* __restrict__ x, const float* __restrict__ g,
                     const float* __restrict__ b,
                     __nv_bfloat16* __restrict__ xh, __nv_bfloat16* __restrict__ xl) {
    int row = blockIdx.x, tid = threadIdx.x;
    float* r = x + (size_t)row * EE;
    float v0 = r[tid], v1 = r[tid + 256];
    __shared__ float red[256];
    red[tid] = v0 + v1; __syncthreads();
    for (int s = 128; s > 0; s >>= 1) { if (tid < s) red[tid] += red[tid + s]; __syncthreads(); }
    float m = red[0] * (1.0f / 512.0f);
    __syncthreads();
    float d0 = v0 - m, d1 = v1 - m;
    red[tid] = d0*d0 + d1*d1; __syncthreads();
    for (int s = 128; s > 0; s >>= 1) { if (tid < s) red[tid] += red[tid + s]; __syncthreads(); }
    float rs = rsqrtf(red[0] * (1.0f / 512.0f) + 1e-5f);
    float o0 = d0 * rs * g[tid]       + b[tid];
    float o1 = d1 * rs * g[tid + 256] + b[tid + 256];
    r[tid] = o0; r[tid + 256] = o1;
    __nv_bfloat16 hh, ll;
    size_t base = (size_t)row * EE;
    split_bf16(o0, hh, ll); xh[base + tid] = hh;       xl[base + tid] = ll;
    split_bf16(o1, hh, ll); xh[base + tid + 256] = hh; xl[base + tid + 256] = ll;
}

// ---------------- final LayerNorm (src already has residual) -> dst --------
__global__ void ln_out_k(const float* __restrict__ a, const float* __restrict__ g,
                         const float* __restrict__ b, float* __restrict__ dst) {
    int row = blockIdx.x, tid = threadIdx.x;
    size_t off = (size_t)row * EE;
    float v0 = a[off + tid], v1 = a[off + tid + 256];
    __shared__ float red[256];
    red[tid] = v0 + v1; __syncthreads();
    for (int s = 128; s > 0; s >>= 1) { if (tid < s) red[tid] += red[tid + s]; __syncthreads(); }
    float m = red[0] * (1.0f / 512.0f);
    __syncthreads();
    float d0 = v0 - m, d1 = v1 - m;
    red[tid] = d0*d0 + d1*d1; __syncthreads();
    for (int s = 128; s > 0; s >>= 1) { if (tid < s) red[tid] += red[tid + s]; __syncthreads(); }
    float rs = rsqrtf(red[0] * (1.0f / 512.0f) + 1e-5f);
    dst[off + tid]       = d0 * rs * g[tid]       + b[tid];
    dst[off + tid + 256] = d1 * rs * g[tid + 256] + b[tid + 256];
}

// ---------------- launch ----------------
static inline void* sym(const void* s) {
    void* p = nullptr;
    cudaGetSymbolAddress(&p, s);
    return p;
}

extern "C" void kernel_launch(void* const* d_in, const int* in_sizes, int n_in,
                              void* d_out, int out_size) {
    const float* x   = (const float*)d_in[0];
    const void*  padsrc = d_in[1];
    const float* ipw = (const float*)d_in[2];  const float* ipb = (const float*)d_in[3];
    const float* mow = (const float*)d_in[4];  const float* mob = (const float*)d_in[5];
    const float* dqw = (const float*)d_in[6];  const float* dqb = (const float*)d_in[7];
    const float* dkw = (const float*)d_in[8];  const float* dkb = (const float*)d_in[9];
    const float* dvw = (const float*)d_in[10]; const float* dvb = (const float*)d_in[11];
    const float* dow = (const float*)d_in[12]; const float* dob = (const float*)d_in[13];
    const float* o1w = (const float*)d_in[14]; const float* o1b = (const float*)d_in[15];
    const float* o2w = (const float*)d_in[16]; const float* o2b = (const float*)d_in[17];
    const float* g1w = (const float*)d_in[18]; const float* g1b = (const float*)d_in[19];
    const float* g2w = (const float*)d_in[20]; const float* g2b = (const float*)d_in[21];
    const float* n1g = (const float*)d_in[22]; const float* n1b = (const float*)d_in[23];
    const float* n2g = (const float*)d_in[24]; const float* n2b = (const float*)d_in[25];
    const float* f1w = (const float*)d_in[26]; const float* f1b = (const float*)d_in[27];
    const float* f2w = (const float*)d_in[28]; const float* f2b = (const float*)d_in[29];
    float* out = (float*)d_out;

    float* qkv   = (float*)sym(g_qkv);
    float* qkvd  = (float*)sym(g_qkvd);
    float* loc   = (float*)sym(g_local);
    float* off2  = (float*)sym(g_off2);
    int*   len   = (int*)  sym(g_len);
    int*   sp    = (int*)  sym(g_sp);
    float* lng   = (float*)sym(g_long);
    float* x1    = (float*)sym(g_x1);
    float* f     = (float*)sym(g_f);
    float* b3    = (float*)sym(g_b3);
    unsigned char* pad = (unsigned char*)sym(g_pad);

    __nv_bfloat16* xh    = (__nv_bfloat16*)sym(g_xh);    __nv_bfloat16* xl    = (__nv_bfloat16*)sym(g_xl);
    __nv_bfloat16* loh   = (__nv_bfloat16*)sym(g_loh);   __nv_bfloat16* lol   = (__nv_bfloat16*)sym(g_lol);
    __nv_bfloat16* loch  = (__nv_bfloat16*)sym(g_loch);  __nv_bfloat16* locl  = (__nv_bfloat16*)sym(g_locl);
    __nv_bfloat16* lngh  = (__nv_bfloat16*)sym(g_lngh);  __nv_bfloat16* lngl  = (__nv_bfloat16*)sym(g_lngl);
    __nv_bfloat16* off1h = (__nv_bfloat16*)sym(g_off1h); __nv_bfloat16* off1l = (__nv_bfloat16*)sym(g_off1l);
    __nv_bfloat16* latth = (__nv_bfloat16*)sym(g_latth); __nv_bfloat16* lattl = (__nv_bfloat16*)sym(g_lattl);
    __nv_bfloat16* g1h   = (__nv_bfloat16*)sym(g_g1h);   __nv_bfloat16* g1l   = (__nv_bfloat16*)sym(g_g1l);
    __nv_bfloat16* x1h   = (__nv_bfloat16*)sym(g_x1h);   __nv_bfloat16* x1l   = (__nv_bfloat16*)sym(g_x1l);
    __nv_bfloat16* f1h   = (__nv_bfloat16*)sym(g_f1h);   __nv_bfloat16* f1l   = (__nv_bfloat16*)sym(g_f1l);
    __nv_bfloat16* wh    = (__nv_bfloat16*)sym(g_wh);    __nv_bfloat16* wl    = (__nv_bfloat16*)sym(g_wl);

    // allow 60KB dynamic smem on all GEMM instantiations (idempotent)
    cudaFuncSetAttribute(bgemm_k<0,1,0,0>, cudaFuncAttributeMaxDynamicSharedMemorySize, SMEM_BYTES);
    cudaFuncSetAttribute(bgemm_k<0,1,1,0>, cudaFuncAttributeMaxDynamicSharedMemorySize, SMEM_BYTES);
    cudaFuncSetAttribute(bgemm_k<1,0,1,0>, cudaFuncAttributeMaxDynamicSharedMemorySize, SMEM_BYTES);
    cudaFuncSetAttribute(bgemm_k<1,0,1,1>, cudaFuncAttributeMaxDynamicSharedMemorySize, SMEM_BYTES);
    cudaFuncSetAttribute(bgemm_k<2,1,0,0>, cudaFuncAttributeMaxDynamicSharedMemorySize, SMEM_BYTES);
    cudaFuncSetAttribute(bgemm_k<3,1,0,0>, cudaFuncAttributeMaxDynamicSharedMemorySize, SMEM_BYTES);

    const int M = MM;
    dim3 thr(256);

    // 0. mask canonicalization
    detect_mask_k<<<1, 256>>>((const unsigned char*)padsrc);
    convert_mask_k<<<(MM + 255)/256, thr>>>(padsrc);

    // 1. merged hi/lo splits (x + 12 weights), one launch
    SplitArgs sa;
    sa.src[0]=x;   sa.dh[0]=xh;          sa.dl[0]=xl;
    sa.src[1]=ipw; sa.dh[1]=wh+OFF_IP;   sa.dl[1]=wl+OFF_IP;
    sa.src[2]=mow; sa.dh[2]=wh+OFF_MO;   sa.dl[2]=wl+OFF_MO;
    sa.src[3]=dqw; sa.dh[3]=wh+OFF_DQ;   sa.dl[3]=wl+OFF_DQ;
    sa.src[4]=dkw; sa.dh[4]=wh+OFF_DK;   sa.dl[4]=wl+OFF_DK;
    sa.src[5]=dvw; sa.dh[5]=wh+OFF_DV;   sa.dl[5]=wl+OFF_DV;
    sa.src[6]=dow; sa.dh[6]=wh+OFF_DO;   sa.dl[6]=wl+OFF_DO;
    sa.src[7]=o1w; sa.dh[7]=wh+OFF_O1;   sa.dl[7]=wl+OFF_O1;
    sa.src[8]=o2w; sa.dh[8]=wh+OFF_O2;   sa.dl[8]=wl+OFF_O2;
    sa.src[9]=g1w; sa.dh[9]=wh+OFF_G1;   sa.dl[9]=wl+OFF_G1;
    sa.src[10]=g2w; sa.dh[10]=wh+OFF_G2; sa.dl[10]=wl+OFF_G2;
    sa.src[11]=f1w; sa.dh[11]=wh+OFF_F1; sa.dl[11]=wl+OFF_F1;
    sa.src[12]=f2w; sa.dh[12]=wh+OFF_F2; sa.dl[12]=wl+OFF_F2;
    megasplit_k<<<SPLIT_BLOCKS, thr>>>(sa);
    bias3_k<<<6, thr>>>(dqb, dkb, dvb, b3);

    // 2. qkv projection (f32)
    bgemm_k<0,1,0,0><<<dim3(E3/64, M/128), thr, SMEM_BYTES>>>(
        xh, xl, nullptr, nullptr, nullptr, nullptr, wh+OFF_IP, wl+OFF_IP, ipb,
        qkv, nullptr, nullptr, nullptr, nullptr, nullptr, M, E3, EE);
    // 3. local attention -> lo hi/lo
    local_attn_k<<<M, 256>>>(qkv, pad, loh, lol);
    // 4. mha out proj -> loc f32 + loch/locl bf16
    bgemm_k<0,1,1,0><<<dim3(EE/64, M/128), thr, SMEM_BYTES>>>(
        loh, lol, nullptr, nullptr, nullptr, nullptr, wh+OFF_MO, wl+OFF_MO, mob,
        loc, loch, locl, nullptr, nullptr, nullptr, M, EE, EE);
    // 5. offset mlp
    bgemm_k<1,0,1,0><<<dim3(EE/64, M/128), thr, SMEM_BYTES>>>(
        xh, xl, nullptr, nullptr, nullptr, nullptr, wh+OFF_O1, wl+OFF_O1, o1b,
        nullptr, off1h, off1l, nullptr, nullptr, nullptr, M, EE, EE);
    bgemm_k<0,1,0,0><<<dim3((HH*PP)/64, M/128), thr, SMEM_BYTES>>>(
        off1h, off1l, nullptr, nullptr, nullptr, nullptr, wh+OFF_O2, wl+OFF_O2, o2b,
        off2, nullptr, nullptr, nullptr, nullptr, nullptr, M, HH*PP, EE);
    // 6. lengths + sampled positions
    lengths_k<<<BB, 256>>>(pad, len);
    sampler_k<<<M, PP>>>(off2, len, sp);
    // 7. merged dq/dk/dv projection (N=1536)
    bgemm_k<0,1,0,0><<<dim3(E3/64, M/128), thr, SMEM_BYTES>>>(
        xh, xl, nullptr, nullptr, nullptr, nullptr, wh+OFF_DQ, wl+OFF_DQ, b3,
        qkvd, nullptr, nullptr, nullptr, nullptr, nullptr, M, E3, EE);
    // 8. long attention -> latt hi/lo; out proj -> lng f32 + lngh/lngl
    long_attn_k<<<M, 128>>>(qkvd, sp, pad, latth, lattl);
    bgemm_k<0,1,1,0><<<dim3(EE/64, M/128), thr, SMEM_BYTES>>>(
        latth, lattl, nullptr, nullptr, nullptr, nullptr, wh+OFF_DO, wl+OFF_DO, dob,
        lng, lngh, lngl, nullptr, nullptr, nullptr, M, EE, EE);
    // 9. gating: gate1 reads [x | loc | lng] segment-wise (no concat buffer)
    bgemm_k<1,0,1,1><<<dim3(EE/64, M/128), thr, SMEM_BYTES>>>(
        xh, xl, loch, locl, lngh, lngl, wh+OFF_G1, wl+OFF_G1, g1b,
        nullptr, g1h, g1l, nullptr, nullptr, nullptr, M, EE, E3);
    //    gate2 + sigmoid + fuse + residual fused in epilogue -> x1
    bgemm_k<2,1,0,0><<<dim3(EE/64, M/128), thr, SMEM_BYTES>>>(
        g1h, g1l, nullptr, nullptr, nullptr, nullptr, wh+OFF_G2, wl+OFF_G2, g2b,
        x1, nullptr, nullptr, x, loc, lng, M, EE, EE);
    ln_k<<<M, 256>>>(x1, n1g, n1b, x1h, x1l);
    // 10. FFN (ffn2 adds x1 residual in epilogue)
    bgemm_k<1,0,1,0><<<dim3(HID/64, M/128), thr, SMEM_BYTES>>>(
        x1h, x1l, nullptr, nullptr, nullptr, nullptr, wh+OFF_F1, wl+OFF_F1, f1b,
        nullptr, f1h, f1l, nullptr, nullptr, nullptr, M, HID, EE);
    bgemm_k<3,1,0,0><<<dim3(EE/64, M/128), thr, SMEM_BYTES>>>(
        f1h, f1l, nullptr, nullptr, nullptr, nullptr, wh+OFF_F2, wl+OFF_F2, f2b,
        f, nullptr, nullptr, x1, nullptr, nullptr, M, EE, HID);
    // 11. final LN -> output
    ln_out_k<<<M, 256>>>(f, n2g, n2b, out);

    (void)in_sizes; (void)n_in; (void)out_size;
}

// round 15
// speedup vs baseline: 1.2862x; 1.0003x over previous
#include <cuda_runtime.h>
#include <cuda_bf16.h>
#include <math.h>
#include <stdint.h>

// ---------------- Problem constants ----------------
#define BB 8
#define SS 1024
#define EE 512
#define HH 8
#define PP 32
#define HID 2048
#define MM (BB*SS)          // 8192 token rows
#define E3 (3*EE)           // 1536

// ---------------- f32 scratch ----------------
__device__ float g_qkv  [MM*E3];
__device__ float g_qkvd [MM*E3];
__device__ float g_local[MM*EE];
__device__ float g_off2 [MM*(HH*PP)];
__device__ int   g_len  [BB];
__device__ int   g_sp   [MM*PP];
__device__ float g_long [MM*EE];
__device__ float g_x1   [MM*EE];
__device__ float g_f    [MM*EE];
__device__ float g_b3   [E3];
__device__ unsigned char g_pad[MM];
__device__ int g_mask_kind;

// ---------------- bf16 hi/lo scratch ----------------
__device__ __align__(16) __nv_bfloat16 g_xh   [MM*EE],  g_xl   [MM*EE];
__device__ __align__(16) __nv_bfloat16 g_loh  [MM*EE],  g_lol  [MM*EE];
__device__ __align__(16) __nv_bfloat16 g_loch [MM*EE],  g_locl [MM*EE];
__device__ __align__(16) __nv_bfloat16 g_lngh [MM*EE],  g_lngl [MM*EE];
__device__ __align__(16) __nv_bfloat16 g_off1h[MM*EE],  g_off1l[MM*EE];
__device__ __align__(16) __nv_bfloat16 g_latth[MM*EE],  g_lattl[MM*EE];
__device__ __align__(16) __nv_bfloat16 g_g1h  [MM*EE],  g_g1l  [MM*EE];
__device__ __align__(16) __nv_bfloat16 g_x1h  [MM*EE],  g_x1l  [MM*EE];
__device__ __align__(16) __nv_bfloat16 g_f1h  [MM*HID], g_f1l  [MM*HID];

// weight pool (hi/lo)
#define WPOOL 5636096
__device__ __align__(16) __nv_bfloat16 g_wh[WPOOL], g_wl[WPOOL];
#define OFF_IP 0
#define OFF_MO 786432
#define OFF_DQ 1048576
#define OFF_DK 1310720
#define OFF_DV 1572864
#define OFF_DO 1835008
#define OFF_O1 2097152
#define OFF_O2 2359296
#define OFF_G1 2490368
#define OFF_G2 3276800
#define OFF_F1 3538944
#define OFF_F2 4587520

// ---------------- helpers ----------------
__device__ __forceinline__ float warp_sum(float v) {
    #pragma unroll
    for (int o = 16; o > 0; o >>= 1) v += __shfl_xor_sync(0xffffffffu, v, o);
    return v;
}
__device__ __forceinline__ float warp_max(float v) {
    #pragma unroll
    for (int o = 16; o > 0; o >>= 1) v = fmaxf(v, __shfl_xor_sync(0xffffffffu, v, o));
    return v;
}
__device__ __forceinline__ float gelu_exact(float x) {
    return 0.5f * x * (1.0f + erff(x * 0.70710678118654752f));
}
__device__ __forceinline__ void split_bf16(float v, __nv_bfloat16& h, __nv_bfloat16& l) {
    h = __float2bfloat16(v);
    l = __float2bfloat16(v - __bfloat162float(h));
}

// ---------------- mask dtype detection + canonicalization ------------------
__global__ void detect_mask_k(const unsigned char* __restrict__ m) {
    __shared__ int s_weird, s_3f_odd, s_nz_off, s_nz;
    if (threadIdx.x == 0) { s_weird = 0; s_3f_odd = 0; s_nz_off = 0; s_nz = 0; }
    __syncthreads();
    int weird = 0, odd3f = 0, nzoff = 0, nz = 0;
    for (int i = threadIdx.x; i < MM; i += blockDim.x) {
        unsigned char v = m[i];
        if (v) {
            nz = 1;
            if (v != 1u) weird = 1;
            if (v == 0x3fu && (i & 1)) odd3f = 1;
            if ((i & 3) && v == 1u) nzoff = 1;
        }
    }
    if (weird) atomicOr(&s_weird, 1);
    if (odd3f) atomicOr(&s_3f_odd, 1);
    if (nzoff) atomicOr(&s_nz_off, 1);
    if (nz)    atomicOr(&s_nz, 1);
    __syncthreads();
    if (threadIdx.x == 0) {
        int kind;
        if (s_weird)        kind = s_3f_odd ? 3 : 2;
        else if (s_nz_off)  kind = 0;
        else if (s_nz)      kind = 1;
        else                kind = 0;
        g_mask_kind = kind;
    }
}
__global__ void convert_mask_k(const void* __restrict__ src) {
    int i = blockIdx.x * blockDim.x + threadIdx.x;
    if (i >= MM) return;
    int kind = g_mask_kind;
    unsigned char v;
    if (kind == 0)      v = (((const unsigned char*)src)[i] != 0);
    else if (kind == 1) v = (((const int*)src)[i] != 0);
    else if (kind == 2) v = (((const float*)src)[i] != 0.0f);
    else                v = (((const unsigned short*)src)[i] != 0);
    g_pad[i] = v;
}

// ---------------- merged hi/lo split: 13 segments, one launch ---------------
#define NSEG 13
struct SplitArgs {
    const float* src[NSEG];
    __nv_bfloat16* dh[NSEG];
    __nv_bfloat16* dl[NSEG];
};
__constant__ int c_cum[NSEG + 1] = {
    0, 16384, 19456, 20480, 21504, 22528, 23552, 24576,
    25600, 26112, 29184, 30208, 34304, 38400 };
#define SPLIT_BLOCKS 38400

__global__ void megasplit_k(SplitArgs args) {
    int blk = blockIdx.x;
    int seg = 0;
    #pragma unroll
    for (int s = 1; s < NSEG; s++) if (blk >= c_cum[s]) seg = s;
    int idx = (blk - c_cum[seg]) * 256 + threadIdx.x;
    float v = args.src[seg][idx];
    __nv_bfloat16 h, l;
    split_bf16(v, h, l);
    args.dh[seg][idx] = h;
    args.dl[seg][idx] = l;
}

// ---------------- bias concat for merged dq/dk/dv GEMM ----------------
__global__ void bias3_k(const float* __restrict__ a, const float* __restrict__ b,
                        const float* __restrict__ c, float* __restrict__ o) {
    int i = blockIdx.x * 256 + threadIdx.x;
    if (i >= E3) return;
    o[i] = (i < 512) ? a[i] : (i < 1024 ? b[i - 512] : c[i - 1024]);
}

// ---------------- 3xBF16 pipelined GEMM ----------------
// C[M,N] = (Ah+Al)[M,K] @ (Wh+Wl)[N,K]^T + bias  (dropping Al*Wl)
// BM=128 BN=64 BK=32, 256 thr, 8 warps (4m x 2n), warp tile 32x32.
// 2-stage cp.async pipeline, ldmatrix fragment loads.
// ACT: 0 none, 1 GELU, 2 gate-fuse (out = P0 + sig(v)*P1 + (1-sig)*P2), 3 v += P0.
// SEG: A operand read segment-wise from (Ah,Al | AhB,AlB | AhC,AlC), each [M,512].
__device__ __forceinline__ void mma_bf16(float* d, const uint32_t* a, const uint32_t* b) {
    asm volatile(
        "mma.sync.aligned.m16n8k16.row.col.f32.bf16.bf16.f32 "
        "{%0,%1,%2,%3}, {%4,%5,%6,%7}, {%8,%9}, {%0,%1,%2,%3};\n"
        : "+f"(d[0]), "+f"(d[1]), "+f"(d[2]), "+f"(d[3])
        : "r"(a[0]), "r"(a[1]), "r"(a[2]), "r"(a[3]), "r"(b[0]), "r"(b[1]));
}
__device__ __forceinline__ void ldsm4(uint32_t* r, uint32_t addr) {
    asm volatile("ldmatrix.sync.aligned.m8n8.x4.shared.b16 {%0,%1,%2,%3}, [%4];\n"
        : "=r"(r[0]), "=r"(r[1]), "=r"(r[2]), "=r"(r[3]) : "r"(addr));
}
__device__ __forceinline__ void cp16(uint32_t dst, const void* src) {
    asm volatile("cp.async.cg.shared.global [%0], [%1], 16;\n" :: "r"(dst), "l"(src));
}
template<int N> __device__ __forceinline__ void cp_wait() {
    asm volatile("cp.async.wait_group %0;\n" :: "n"(N));
}

#define STG_BYTES 30720u   // per stage: Ah 10240 | Al 10240 | Wh 5120 | Wl 5120
#define SMEM_BYTES (2*STG_BYTES)

template<int ACT, int WF32, int WBF16, int SEG>
__global__ void __launch_bounds__(256, 2)
bgemm_k(const __nv_bfloat16* __restrict__ Ah, const __nv_bfloat16* __restrict__ Al,
        const __nv_bfloat16* __restrict__ AhB, const __nv_bfloat16* __restrict__ AlB,
        const __nv_bfloat16* __restrict__ AhC, const __nv_bfloat16* __restrict__ AlC,
        const __nv_bfloat16* __restrict__ Wh, const __nv_bfloat16* __restrict__ Wl,
        const float* __restrict__ bias, float* __restrict__ C,
        __nv_bfloat16* __restrict__ Ch, __nv_bfloat16* __restrict__ Cl,
        const float* __restrict__ P0, const float* __restrict__ P1,
        const float* __restrict__ P2,
        int M, int N, int K)
{
    extern __shared__ __align__(16) char dynsm[];
    const uint32_t smem_u32 = (uint32_t)__cvta_generic_to_shared(dynsm);

    const int m0 = blockIdx.y * 128;
    const int n0 = blockIdx.x * 64;
    const int tid  = threadIdx.x;
    const int warp = tid >> 5, lane = tid & 31;
    const int wm = warp >> 1, wn = warp & 1;
    const int g  = lane >> 2, t4 = lane & 3;

    float acc[2][4][4];
    #pragma unroll
    for (int i = 0; i < 2; i++)
        #pragma unroll
        for (int j = 0; j < 4; j++)
            #pragma unroll
            for (int r = 0; r < 4; r++) acc[i][j][r] = 0.0f;

    const int lr = tid >> 2;           // 0..63
    const int c8 = (tid & 3) << 3;     // 0,8,16,24

    auto load_stage = [&](int stage, int k0) {
        uint32_t sb = smem_u32 + (uint32_t)stage * STG_BYTES;
        const __nv_bfloat16* pAh = Ah;
        const __nv_bfloat16* pAl = Al;
        int kl = k0;
        size_t as = (size_t)K;
        if (SEG) {
            as = 512;
            if (k0 >= 1024)     { pAh = AhC; pAl = AlC; kl = k0 - 1024; }
            else if (k0 >= 512) { pAh = AhB; pAl = AlB; kl = k0 - 512; }
        }
        uint32_t dA = sb + (uint32_t)(lr * 80 + c8 * 2);
        cp16(dA,                pAh + (size_t)(m0 + lr) * as + kl + c8);
        cp16(dA + 64u*80u,      pAh + (size_t)(m0 + lr + 64) * as + kl + c8);
        cp16(dA + 10240u,       pAl + (size_t)(m0 + lr) * as + kl + c8);
        cp16(dA + 10240u + 64u*80u, pAl + (size_t)(m0 + lr + 64) * as + kl + c8);
        uint32_t dW = sb + 20480u + (uint32_t)(lr * 80 + c8 * 2);
        cp16(dW,           Wh + (size_t)(n0 + lr) * K + k0 + c8);
        cp16(dW + 5120u,   Wl + (size_t)(n0 + lr) * K + k0 + c8);
    };

    // lane-invariant fragment base offsets (within a stage)
    const uint32_t aOff = (uint32_t)((wm*32 + (lane & 15)) * 80 + ((lane >> 4) << 3) * 2);
    const uint32_t bOff = 20480u + (uint32_t)(
        ((wn*32) + (lane & 7) + (((lane >> 4) & 1) << 3)) * 80 + (((lane >> 3) & 1) << 3) * 2);

    load_stage(0, 0);
    asm volatile("cp.async.commit_group;\n");
    const int niter = K >> 5;

    for (int it = 0; it < niter; ++it) {
        if (it + 1 < niter) {
            load_stage((it + 1) & 1, (it + 1) << 5);
            asm volatile("cp.async.commit_group;\n");
            cp_wait<1>();
        } else {
            cp_wait<0>();
        }
        __syncthreads();

        uint32_t sb = smem_u32 + (uint32_t)(it & 1) * STG_BYTES;
        uint32_t aB = sb + aOff;
        uint32_t bB = sb + bOff;
        #pragma unroll
        for (int kk = 0; kk < 32; kk += 16) {
            uint32_t ah[2][4], alr[2][4], bh[2][4], blr[2][4];
            ldsm4(ah[0],  aB + kk*2);
            ldsm4(ah[1],  aB + 1280u + kk*2);
            ldsm4(alr[0], aB + 10240u + kk*2);
            ldsm4(alr[1], aB + 10240u + 1280u + kk*2);
            ldsm4(bh[0],  bB + kk*2);
            ldsm4(bh[1],  bB + 1280u + kk*2);
            ldsm4(blr[0], bB + 5120u + kk*2);
            ldsm4(blr[1], bB + 5120u + 1280u + kk*2);
            #pragma unroll
            for (int i = 0; i < 2; i++)
                #pragma unroll
                for (int jp = 0; jp < 2; jp++) {
                    mma_bf16(acc[i][jp*2],   ah[i],  &bh[jp][0]);
                    mma_bf16(acc[i][jp*2+1], ah[i],  &bh[jp][2]);
                    mma_bf16(acc[i][jp*2],   ah[i],  &blr[jp][0]);
                    mma_bf16(acc[i][jp*2+1], ah[i],  &blr[jp][2]);
                    mma_bf16(acc[i][jp*2],   alr[i], &bh[jp][0]);
                    mma_bf16(acc[i][jp*2+1], alr[i], &bh[jp][2]);
                }
        }
        __syncthreads();
    }

    // epilogue
    #pragma unroll
    for (int i = 0; i < 2; i++) {
        int r0 = m0 + wm * 32 + i * 16 + g;
        #pragma unroll
        for (int j = 0; j < 4; j++) {
            int c = n0 + wn * 32 + j * 8 + 2 * t4;
            float b0 = bias[c], b1 = bias[c + 1];
            float v00 = acc[i][j][0] + b0, v01 = acc[i][j][1] + b1;
            float v10 = acc[i][j][2] + b0, v11 = acc[i][j][3] + b1;
            size_t i0 = (size_t)r0 * N + c, i1 = (size_t)(r0 + 8) * N + c;
            if (ACT == 1) {
                v00 = gelu_exact(v00); v01 = gelu_exact(v01);
                v10 = gelu_exact(v10); v11 = gelu_exact(v11);
            }
            if (ACT == 2) {
                float s00 = 1.0f/(1.0f + expf(-v00)), s01 = 1.0f/(1.0f + expf(-v01));
                float s10 = 1.0f/(1.0f + expf(-v10)), s11 = 1.0f/(1.0f + expf(-v11));
                v00 = P0[i0]   + s00 * P1[i0]   + (1.0f - s00) * P2[i0];
                v01 = P0[i0+1] + s01 * P1[i0+1] + (1.0f - s01) * P2[i0+1];
                v10 = P0[i1]   + s10 * P1[i1]   + (1.0f - s10) * P2[i1];
                v11 = P0[i1+1] + s11 * P1[i1+1] + (1.0f - s11) * P2[i1+1];
            }
            if (ACT == 3) {
                v00 += P0[i0]; v01 += P0[i0+1]; v10 += P0[i1]; v11 += P0[i1+1];
            }
            if (WF32) {
                *(float2*)&C[i0] = make_float2(v00, v01);
                *(float2*)&C[i1] = make_float2(v10, v11);
            }
            if (WBF16) {
                __nv_bfloat16 h0, l0, h1, l1;
                split_bf16(v00, h0, l0); split_bf16(v01, h1, l1);
                *(__nv_bfloat162*)&Ch[i0] = __nv_bfloat162(h0, h1);
                *(__nv_bfloat162*)&Cl[i0] = __nv_bfloat162(l0, l1);
                split_bf16(v10, h0, l0); split_bf16(v11, h1, l1);
                *(__nv_bfloat162*)&Ch[i1] = __nv_bfloat162(h0, h1);
                *(__nv_bfloat162*)&Cl[i1] = __nv_bfloat162(l0, l1);
            }
        }
    }
}

// ---------------- Local windowed attention (window = 4) -> lo hi/lo --------
__global__ void local_attn_k(const float* __restrict__ qkv,
                             const unsigned char* __restrict__ pad,
                             __nv_bfloat16* __restrict__ loh,
                             __nv_bfloat16* __restrict__ lol) {
    int bq = blockIdx.x;
    int b = bq >> 10, q = bq & 1023;
    int h = threadIdx.x >> 5, lane = threadIdx.x & 31;

    const float* qr = qkv + (size_t)bq * E3 + h * 64;
    float q0 = qr[lane], q1 = qr[lane + 32];
    const float* rowbase = qkv + (size_t)(b << 10) * E3;

    float sc[4];
    #pragma unroll
    for (int w = 0; w < 4; w++) {
        int kp = q - 3 + w;
        bool valid = (kp >= 0) && (pad[(b << 10) + kp] == 0);
        float s = -INFINITY;
        if (valid) {
            const float* kr = rowbase + (size_t)kp * E3 + EE + h * 64;
            float d = q0 * kr[lane] + q1 * kr[lane + 32];
            d = warp_sum(d);
            s = d * 0.125f;
        }
        sc[w] = s;
    }
    float mx = fmaxf(fmaxf(sc[0], sc[1]), fmaxf(sc[2], sc[3]));
    float o0 = 0.0f, o1 = 0.0f;
    if (mx != -INFINITY) {
        float p[4], psum = 0.0f;
        #pragma unroll
        for (int w = 0; w < 4; w++) {
            p[w] = (sc[w] == -INFINITY) ? 0.0f : expf(sc[w] - mx);
            psum += p[w];
        }
        float inv = 1.0f / psum;
        #pragma unroll
        for (int w = 0; w < 4; w++) {
            if (p[w] != 0.0f) {
                const float* vr = rowbase + (size_t)(q - 3 + w) * E3 + 2*EE + h * 64;
                float pw = p[w] * inv;
                o0 = fmaf(pw, vr[lane], o0);
                o1 = fmaf(pw, vr[lane + 32], o1);
            }
        }
    }
    size_t i0 = (size_t)bq * EE + h * 64 + lane;
    __nv_bfloat16 hh, ll;
    split_bf16(o0, hh, ll); loh[i0] = hh;      lol[i0] = ll;
    split_bf16(o1, hh, ll); loh[i0 + 32] = hh; lol[i0 + 32] = ll;
}

// ---------------- lengths ----------------
__global__ void lengths_k(const unsigned char* __restrict__ pad, int* __restrict__ len) {
    int b = blockIdx.x, tid = threadIdx.x;
    __shared__ int red[256];
    int c = 0;
    for (int i = tid; i < SS; i += 256) c += (pad[b * SS + i] != 0);
    red[tid] = c; __syncthreads();
    for (int s = 128; s > 0; s >>= 1) { if (tid < s) red[tid] += red[tid + s]; __syncthreads(); }
    if (tid == 0) { int l = SS - red[0]; len[b] = l < 1 ? 1 : l; }
}

// ---------------- sampler ----------------
__global__ void sampler_k(const float* __restrict__ off2, const int* __restrict__ len,
                          int* __restrict__ sp) {
    int bq = blockIdx.x, b = bq >> 10, q = bq & 1023;
    int p = threadIdx.x;
    const float* r = off2 + (size_t)bq * (HH * PP);
    float o = 0.0f;
    #pragma unroll
    for (int h = 0; h < HH; h++) o += tanhf(r[h * PP + p]);
    float posf = (float)q;
    float delta = __fadd_rn(0.9f, -0.1f);
    float step  = __fdiv_rn(delta, 31.0f);
    float anchor = __fadd_rn(0.1f, __fmul_rn((float)p, step));
    float base = __fmul_rn(anchor, posf);
    float s = __fadd_rn(base, o);
    float lower = fmaxf(posf - 256.0f, 0.0f);
    s = fminf(fmaxf(s, lower), posf);
    s = fminf(s, (float)(len[b] - 1));
    sp[(size_t)bq * PP + p] = (int)rintf(s);
}

// ---------------- long deformable attention (qkvd stride E3) ---------------
__global__ void long_attn_k(const float* __restrict__ qkvd, const int* __restrict__ sp,
                            const unsigned char* __restrict__ pad,
                            __nv_bfloat16* __restrict__ outh,
                            __nv_bfloat16* __restrict__ outl) {
    int bq = blockIdx.x, b = bq >> 10, q = bq & 1023;
    __shared__ float qs[EE];
    __shared__ float pa[PP];
    __shared__ int sps[PP];
    int tid = threadIdx.x;
    const float* qr = qkvd + (size_t)bq * E3;                // qd at offset 0
    for (int e = tid; e < EE; e += 128) qs[e] = qr[e];
    if (tid < PP) sps[tid] = sp[(size_t)bq * PP + tid];
    __syncthreads();

    int warp = tid >> 5, lane = tid & 31;
    int rb = q - 3; if (rb < 0) rb = 0;
    for (int p = warp; p < PP; p += 4) {
        int s = sps[p];
        bool inv = (pad[(b << 10) + s] != 0) || (s > q) || (s >= rb);
        float val = -INFINITY;
        if (!inv) {
            const float* kr = qkvd + (size_t)((b << 10) + s) * E3 + EE;   // kd
            float d = 0.0f;
            #pragma unroll 4
            for (int e = lane; e < EE; e += 32) d = fmaf(qs[e], kr[e], d);
            d = warp_sum(d);
            val = d * 0.04419417382415922f;
        }
        if (lane == 0) pa[p] = val;
    }
    __syncthreads();
    if (tid < 32) {
        float v = pa[tid];
        float mx = warp_max(v);
        float e = (mx == -INFINITY) ? 0.0f : expf(v - mx);
        float sum = warp_sum(e);
        pa[tid] = (sum > 0.0f) ? e / sum : 0.0f;
    }
    __syncthreads();
    const float* vb = qkvd + (size_t)(b << 10) * E3 + 2*EE;   // vd
    for (int e = tid; e < EE; e += 128) {
        float acc = 0.0f;
        #pragma unroll
        for (int p = 0; p < PP; p++) {
            float ap = pa[p];
            if (ap != 0.0f) acc = fmaf(ap, vb[(size_t)sps[p] * E3 + e], acc);
        }
        __nv_bfloat16 hh, ll;
        split_bf16(acc, hh, ll);
        outh[(size_t)bq * EE + e] = hh;
        outl[(size_t)bq * EE + e] = ll;
    }
}

// ---------------- LayerNorm in-place + hi/lo emit ----------------
__global__ void ln_k(float* __restrict__ x, const float* __restrict__ g,
                     const float* __restrict__ b,
                     __nv_bfloat16* __restrict__ xh, __nv_bfloat16* __restrict__ xl) {
    int row = blockIdx.x, tid = threadIdx.x;
    float* r = x + (size_t)row * EE;
    float v0 = r[tid], v1 = r[tid + 256];
    __shared__ float red[256];
    red[tid] = v0 + v1; __syncthreads();
    for (int s = 128; s > 0; s >>= 1) { if (tid < s) red[tid] += red[tid + s]; __syncthreads(); }
    float m = red[0] * (1.0f / 512.0f);
    __syncthreads();
    float d0 = v0 - m, d1 = v1 - m;
    red[tid] = d0*d0 + d1*d1; __syncthreads();
    for (int s = 128; s > 0; s >>= 1) { if (tid < s) red[tid] += red[tid + s]; __syncthreads(); }
    float rs = rsqrtf(red[0] * (1.0f / 512.0f) + 1e-5f);
    float o0 = d0 * rs * g[tid]       + b[tid];
    float o1 = d1 * rs * g[tid + 256] + b[tid + 256];
    r[tid] = o0; r[tid + 256] = o1;
    __nv_bfloat16 hh, ll;
    size_t base = (size_t)row * EE;
    split_bf16(o0, hh, ll); xh[base + tid] = hh;       xl[base + tid] = ll;
    split_bf16(o1, hh, ll); xh[base + tid + 256] = hh; xl[base + tid + 256] = ll;
}

// ---------------- final LayerNorm (src already has residual) -> dst --------
__global__ void ln_out_k(const float* __restrict__ a, const float* __restrict__ g,
                         const float* __restrict__ b, float* __restrict__ dst) {
    int row = blockIdx.x, tid = threadIdx.x;
    size_t off = (size_t)row * EE;
    float v0 = a[off + tid], v1 = a[off + tid + 256];
    __shared__ float red[256];
    red[tid] = v0 + v1; __syncthreads();
    for (int s = 128; s > 0; s >>= 1) { if (tid < s) red[tid] += red[tid + s]; __syncthreads(); }
    float m = red[0] * (1.0f / 512.0f);
    __syncthreads();
    float d0 = v0 - m, d1 = v1 - m;
    red[tid] = d0*d0 + d1*d1; __syncthreads();
    for (int s = 128; s > 0; s >>= 1) { if (tid < s) red[tid] += red[tid + s]; __syncthreads(); }
    float rs = rsqrtf(red[0] * (1.0f / 512.0f) + 1e-5f);
    dst[off + tid]       = d0 * rs * g[tid]       + b[tid];
    dst[off + tid + 256] = d1 * rs * g[tid + 256] + b[tid + 256];
}

// ---------------- launch ----------------
static inline void* sym(const void* s) {
    void* p = nullptr;
    cudaGetSymbolAddress(&p, s);
    return p;
}

extern "C" void kernel_launch(void* const* d_in, const int* in_sizes, int n_in,
                              void* d_out, int out_size) {
    const float* x   = (const float*)d_in[0];
    const void*  padsrc = d_in[1];
    const float* ipw = (const float*)d_in[2];  const float* ipb = (const float*)d_in[3];
    const float* mow = (const float*)d_in[4];  const float* mob = (const float*)d_in[5];
    const float* dqw = (const float*)d_in[6];  const float* dqb = (const float*)d_in[7];
    const float* dkw = (const float*)d_in[8];  const float* dkb = (const float*)d_in[9];
    const float* dvw = (const float*)d_in[10]; const float* dvb = (const float*)d_in[11];
    const float* dow = (const float*)d_in[12]; const float* dob = (const float*)d_in[13];
    const float* o1w = (const float*)d_in[14]; const float* o1b = (const float*)d_in[15];
    const float* o2w = (const float*)d_in[16]; const float* o2b = (const float*)d_in[17];
    const float* g1w = (const float*)d_in[18]; const float* g1b = (const float*)d_in[19];
    const float* g2w = (const float*)d_in[20]; const float* g2b = (const float*)d_in[21];
    const float* n1g = (const float*)d_in[22]; const float* n1b = (const float*)d_in[23];
    const float* n2g = (const float*)d_in[24]; const float* n2b = (const float*)d_in[25];
    const float* f1w = (const float*)d_in[26]; const float* f1b = (const float*)d_in[27];
    const float* f2w = (const float*)d_in[28]; const float* f2b = (const float*)d_in[29];
    float* out = (float*)d_out;

    float* qkv   = (float*)sym(g_qkv);
    float* qkvd  = (float*)sym(g_qkvd);
    float* loc   = (float*)sym(g_local);
    float* off2  = (float*)sym(g_off2);
    int*   len   = (int*)  sym(g_len);
    int*   sp    = (int*)  sym(g_sp);
    float* lng   = (float*)sym(g_long);
    float* x1    = (float*)sym(g_x1);
    float* f     = (float*)sym(g_f);
    float* b3    = (float*)sym(g_b3);
    unsigned char* pad = (unsigned char*)sym(g_pad);

    __nv_bfloat16* xh    = (__nv_bfloat16*)sym(g_xh);    __nv_bfloat16* xl    = (__nv_bfloat16*)sym(g_xl);
    __nv_bfloat16* loh   = (__nv_bfloat16*)sym(g_loh);   __nv_bfloat16* lol   = (__nv_bfloat16*)sym(g_lol);
    __nv_bfloat16* loch  = (__nv_bfloat16*)sym(g_loch);  __nv_bfloat16* locl  = (__nv_bfloat16*)sym(g_locl);
    __nv_bfloat16* lngh  = (__nv_bfloat16*)sym(g_lngh);  __nv_bfloat16* lngl  = (__nv_bfloat16*)sym(g_lngl);
    __nv_bfloat16* off1h = (__nv_bfloat16*)sym(g_off1h); __nv_bfloat16* off1l = (__nv_bfloat16*)sym(g_off1l);
    __nv_bfloat16* latth = (__nv_bfloat16*)sym(g_latth); __nv_bfloat16* lattl = (__nv_bfloat16*)sym(g_lattl);
    __nv_bfloat16* g1h   = (__nv_bfloat16*)sym(g_g1h);   __nv_bfloat16* g1l   = (__nv_bfloat16*)sym(g_g1l);
    __nv_bfloat16* x1h   = (__nv_bfloat16*)sym(g_x1h);   __nv_bfloat16* x1l   = (__nv_bfloat16*)sym(g_x1l);
    __nv_bfloat16* f1h   = (__nv_bfloat16*)sym(g_f1h);   __nv_bfloat16* f1l   = (__nv_bfloat16*)sym(g_f1l);
    __nv_bfloat16* wh    = (__nv_bfloat16*)sym(g_wh);    __nv_bfloat16* wl    = (__nv_bfloat16*)sym(g_wl);

    // allow 60KB dynamic smem on all GEMM instantiations (idempotent)
    cudaFuncSetAttribute(bgemm_k<0,1,0,0>, cudaFuncAttributeMaxDynamicSharedMemorySize, SMEM_BYTES);
    cudaFuncSetAttribute(bgemm_k<0,1,1,0>, cudaFuncAttributeMaxDynamicSharedMemorySize, SMEM_BYTES);
    cudaFuncSetAttribute(bgemm_k<1,0,1,0>, cudaFuncAttributeMaxDynamicSharedMemorySize, SMEM_BYTES);
    cudaFuncSetAttribute(bgemm_k<1,0,1,1>, cudaFuncAttributeMaxDynamicSharedMemorySize, SMEM_BYTES);
    cudaFuncSetAttribute(bgemm_k<2,1,0,0>, cudaFuncAttributeMaxDynamicSharedMemorySize, SMEM_BYTES);
    cudaFuncSetAttribute(bgemm_k<3,1,0,0>, cudaFuncAttributeMaxDynamicSharedMemorySize, SMEM_BYTES);

    const int M = MM;
    dim3 thr(256);

    // 0. mask canonicalization
    detect_mask_k<<<1, 256>>>((const unsigned char*)padsrc);
    convert_mask_k<<<(MM + 255)/256, thr>>>(padsrc);

    // 1. merged hi/lo splits (x + 12 weights), one launch
    SplitArgs sa;
    sa.src[0]=x;   sa.dh[0]=xh;          sa.dl[0]=xl;
    sa.src[1]=ipw; sa.dh[1]=wh+OFF_IP;   sa.dl[1]=wl+OFF_IP;
    sa.src[2]=mow; sa.dh[2]=wh+OFF_MO;   sa.dl[2]=wl+OFF_MO;
    sa.src[3]=dqw; sa.dh[3]=wh+OFF_DQ;   sa.dl[3]=wl+OFF_DQ;
    sa.src[4]=dkw; sa.dh[4]=wh+OFF_DK;   sa.dl[4]=wl+OFF_DK;
    sa.src[5]=dvw; sa.dh[5]=wh+OFF_DV;   sa.dl[5]=wl+OFF_DV;
    sa.src[6]=dow; sa.dh[6]=wh+OFF_DO;   sa.dl[6]=wl+OFF_DO;
    sa.src[7]=o1w; sa.dh[7]=wh+OFF_O1;   sa.dl[7]=wl+OFF_O1;
    sa.src[8]=o2w; sa.dh[8]=wh+OFF_O2;   sa.dl[8]=wl+OFF_O2;
    sa.src[9]=g1w; sa.dh[9]=wh+OFF_G1;   sa.dl[9]=wl+OFF_G1;
    sa.src[10]=g2w; sa.dh[10]=wh+OFF_G2; sa.dl[10]=wl+OFF_G2;
    sa.src[11]=f1w; sa.dh[11]=wh+OFF_F1; sa.dl[11]=wl+OFF_F1;
    sa.src[12]=f2w; sa.dh[12]=wh+OFF_F2; sa.dl[12]=wl+OFF_F2;
    megasplit_k<<<SPLIT_BLOCKS, thr>>>(sa);
    bias3_k<<<6, thr>>>(dqb, dkb, dvb, b3);

    // 2. qkv projection (f32)
    bgemm_k<0,1,0,0><<<dim3(E3/64, M/128), thr, SMEM_BYTES>>>(
        xh, xl, nullptr, nullptr, nullptr, nullptr, wh+OFF_IP, wl+OFF_IP, ipb,
        qkv, nullptr, nullptr, nullptr, nullptr, nullptr, M, E3, EE);
    // 3. local attention -> lo hi/lo
    local_attn_k<<<M, 256>>>(qkv, pad, loh, lol);
    // 4. mha out proj -> loc f32 + loch/locl bf16
    bgemm_k<0,1,1,0><<<dim3(EE/64, M/128), thr, SMEM_BYTES>>>(
        loh, lol, nullptr, nullptr, nullptr, nullptr, wh+OFF_MO, wl+OFF_MO, mob,
        loc, loch, locl, nullptr, nullptr, nullptr, M, EE, EE);
    // 5. offset mlp
    bgemm_k<1,0,1,0><<<dim3(EE/64, M/128), thr, SMEM_BYTES>>>(
        xh, xl, nullptr, nullptr, nullptr, nullptr, wh+OFF_O1, wl+OFF_O1, o1b,
        nullptr, off1h, off1l, nullptr, nullptr, nullptr, M, EE, EE);
    bgemm_k<0,1,0,0><<<dim3((HH*PP)/64, M/128), thr, SMEM_BYTES>>>(
        off1h, off1l, nullptr, nullptr, nullptr, nullptr, wh+OFF_O2, wl+OFF_O2, o2b,
        off2, nullptr, nullptr, nullptr, nullptr, nullptr, M, HH*PP, EE);
    // 6. lengths + sampled positions
    lengths_k<<<BB, 256>>>(pad, len);
    sampler_k<<<M, PP>>>(off2, len, sp);
    // 7. merged dq/dk/dv projection (N=1536)
    bgemm_k<0,1,0,0><<<dim3(E3/64, M/128), thr, SMEM_BYTES>>>(
        xh, xl, nullptr, nullptr, nullptr, nullptr, wh+OFF_DQ, wl+OFF_DQ, b3,
        qkvd, nullptr, nullptr, nullptr, nullptr, nullptr, M, E3, EE);
    // 8. long attention -> latt hi/lo; out proj -> lng f32 + lngh/lngl
    long_attn_k<<<M, 128>>>(qkvd, sp, pad, latth, lattl);
    bgemm_k<0,1,1,0><<<dim3(EE/64, M/128), thr, SMEM_BYTES>>>(
        latth, lattl, nullptr, nullptr, nullptr, nullptr, wh+OFF_DO, wl+OFF_DO, dob,
        lng, lngh, lngl, nullptr, nullptr, nullptr, M, EE, EE);
    // 9. gating: gate1 reads [x | loc | lng] segment-wise (no concat buffer)
    bgemm_k<1,0,1,1><<<dim3(EE/64, M/128), thr, SMEM_BYTES>>>(
        xh, xl, loch, locl, lngh, lngl, wh+OFF_G1, wl+OFF_G1, g1b,
        nullptr, g1h, g1l, nullptr, nullptr, nullptr, M, EE, E3);
    //    gate2 + sigmoid + fuse + residual fused in epilogue -> x1
    bgemm_k<2,1,0,0><<<dim3(EE/64, M/128), thr, SMEM_BYTES>>>(
        g1h, g1l, nullptr, nullptr, nullptr, nullptr, wh+OFF_G2, wl+OFF_G2, g2b,
        x1, nullptr, nullptr, x, loc, lng, M, EE, EE);
    ln_k<<<M, 256>>>(x1, n1g, n1b, x1h, x1l);
    // 10. FFN (ffn2 adds x1 residual in epilogue)
    bgemm_k<1,0,1,0><<<dim3(HID/64, M/128), thr, SMEM_BYTES>>>(
        x1h, x1l, nullptr, nullptr, nullptr, nullptr, wh+OFF_F1, wl+OFF_F1, f1b,
        nullptr, f1h, f1l, nullptr, nullptr, nullptr, M, HID, EE);
    bgemm_k<3,1,0,0><<<dim3(EE/64, M/128), thr, SMEM_BYTES>>>(
        f1h, f1l, nullptr, nullptr, nullptr, nullptr, wh+OFF_F2, wl+OFF_F2, f2b,
        f, nullptr, nullptr, x1, nullptr, nullptr, M, EE, HID);
    // 11. final LN -> output
    ln_out_k<<<M, 256>>>(f, n2g, n2b, out);

    (void)in_sizes; (void)n_in; (void)out_size;
}